// round 4
// baseline (speedup 1.0000x reference)
#include <cuda_runtime.h>
#include <cuda_fp16.h>
#include <cstdint>

#define NOBJ 1024
#define TPB  256
#define WST  72        // SMEM weight row stride (halfs): 144B -> conflict-free

// partial[m][jc][i][50]  (fully overwritten every launch by the 512 CTAs)
__device__ float g_partial[8 * 8 * NOBJ * 50];

// ---------------------------------------------------------------------------
// mma.m16n8k16 row.col f32.f16.f16.f32
// A frag (4 b32): a0=(row g, k=2t4,2t4+1) a1=(g+8, same) a2=(g, +8) a3=(g+8, +8)
// B frag (2 b32): b0=(k=2t4,2t4+1, n=g)   b1=(k=+8, n=g)
// C frag (4 f32): c0=(g, n=2t4) c1=(g, 2t4+1) c2=(g+8, 2t4) c3=(g+8, 2t4+1)
// ---------------------------------------------------------------------------
__device__ __forceinline__ void mma16816(float c[4], const uint32_t a[4],
                                         uint32_t b0, uint32_t b1)
{
    asm("mma.sync.aligned.m16n8k16.row.col.f32.f16.f16.f32 "
        "{%0,%1,%2,%3}, {%4,%5,%6,%7}, {%8,%9}, {%0,%1,%2,%3};\n"
        : "+f"(c[0]), "+f"(c[1]), "+f"(c[2]), "+f"(c[3])
        : "r"(a[0]), "r"(a[1]), "r"(a[2]), "r"(a[3]), "r"(b0), "r"(b1));
}

// split (x,y) into fp16 hi pair + fp16 lo (residual) pair, packed as b32
__device__ __forceinline__ void split2(float x, float y, uint32_t& hi, uint32_t& lo)
{
    half2 h = __floats2half2_rn(x, y);
    float2 f = __half22float2(h);
    half2 l = __floats2half2_rn(x - f.x, y - f.y);
    hi = *reinterpret_cast<uint32_t*>(&h);
    lo = *reinterpret_cast<uint32_t*>(&l);
}

__device__ __forceinline__ void split_w(float v, half& hi, half& lo)
{
    hi = __float2half_rn(v);
    lo = __float2half_rn(v - __half2float(hi));
}

__global__ void __launch_bounds__(TPB, 2)
pair_kernel(const float* __restrict__ obj0, const float* __restrict__ obj1,
            const float* __restrict__ prev0, const float* __restrict__ prev1,
            const float* __restrict__ gW0, const float* __restrict__ gb0,
            const float* __restrict__ gW1, const float* __restrict__ gb1,
            const float* __restrict__ gW2, const float* __restrict__ gb2)
{
    const int m  = blockIdx.x;   // module (actor class = m>>1, actee class = m&1)
    const int ib = blockIdx.y;   // i-block (128 actees)
    const int jc = blockIdx.z;   // j-chunk (128 actors)
    const int t  = threadIdx.x;
    const int w  = t >> 5;
    const int lane = t & 31;
    const int t4 = lane & 3;
    const int g  = lane >> 2;

    const int ac = m >> 1;
    const float* actor = (ac == 0) ? obj0 : (ac == 1) ? obj1 : (ac == 2) ? prev0 : prev1;
    const float* actee = (m & 1) ? obj1 : obj0;

    // Transposed, padded weights: Wt[n][k] = W[k][n]; row 50 of W carries bias.
    __shared__ half Wt1hi[64 * WST], Wt1lo[64 * WST];
    __shared__ half Wt2hi[64 * WST], Wt2lo[64 * WST];
    __shared__ float alph[128];
    __shared__ float p_[64], q_[64], r_[64];   // layer-1 rank-1 constants (fp32)

    for (int x = t; x < 64 * WST; x += TPB) {
        Wt1hi[x] = __float2half(0.f);  Wt1lo[x] = __float2half(0.f);
        Wt2hi[x] = __float2half(0.f);  Wt2lo[x] = __float2half(0.f);
    }
    if (t < 64) {
        p_[t] = (t < 50) ? gW0[m * 100 + t]      : 0.f;     // W0[m][0][t]
        q_[t] = (t < 50) ? gW0[m * 100 + 50 + t] : 0.f;     // W0[m][1][t]
        r_[t] = (t < 50) ? gb0[m * 50 + t] : (t == 50 ? 1.f : 0.f);  // bias-feed col
    }
    if (t < 128) alph[t] = actor[jc * 128 + t];
    __syncthreads();
    for (int x = t; x < 51 * 50; x += TPB) {
        int k = x / 50, n = x % 50;
        float w1 = (k < 50) ? gW1[m * 2500 + k * 50 + n] : gb1[m * 50 + n];
        float w2 = (k < 50) ? gW2[m * 2500 + k * 50 + n] : gb2[m * 50 + n];
        half hi, lo;
        split_w(w1, hi, lo);  Wt1hi[n * WST + k] = hi;  Wt1lo[n * WST + k] = lo;
        split_w(w2, hi, lo);  Wt2hi[n * WST + k] = hi;  Wt2lo[n * WST + k] = lo;
    }

    const float betaA = actee[ib * 128 + w * 16 + g];
    const float betaB = actee[ib * 128 + w * 16 + g + 8];

    float Fr[28];
#pragma unroll
    for (int x = 0; x < 28; x++) Fr[x] = 0.f;

    // A3 kt=3 upper slots (k=56..63) are always zero (nt=7 trimmed away)
    uint32_t A3h[4][4], A3l[4][4];
    A3h[3][2] = A3h[3][3] = A3l[3][2] = A3l[3][3] = 0u;

    __syncthreads();    // the ONLY barrier before the writeback

    for (int jj = 0; jj < 128; ++jj) {
        const float al = alph[jj];

        // ---- layer 1 (rank-1 collapse) -> A fragments, all in registers ----
        uint32_t A2h[4][4], A2l[4][4];
#pragma unroll
        for (int kt = 0; kt < 4; kt++) {
            const int c0i = kt * 16 + 2 * t4;       // cols c, c+1, c+8, c+9
            float u0 = fmaf(al, p_[c0i],     r_[c0i]);
            float u1 = fmaf(al, p_[c0i + 1], r_[c0i + 1]);
            float u2 = fmaf(al, p_[c0i + 8], r_[c0i + 8]);
            float u3 = fmaf(al, p_[c0i + 9], r_[c0i + 9]);
            float q0 = q_[c0i], q1 = q_[c0i + 1], q2 = q_[c0i + 8], q3 = q_[c0i + 9];
            float vA0 = fmaxf(fmaf(betaA, q0, u0), 0.f);
            float vA1 = fmaxf(fmaf(betaA, q1, u1), 0.f);
            float vA2 = fmaxf(fmaf(betaA, q2, u2), 0.f);
            float vA3 = fmaxf(fmaf(betaA, q3, u3), 0.f);
            float vB0 = fmaxf(fmaf(betaB, q0, u0), 0.f);
            float vB1 = fmaxf(fmaf(betaB, q1, u1), 0.f);
            float vB2 = fmaxf(fmaf(betaB, q2, u2), 0.f);
            float vB3 = fmaxf(fmaf(betaB, q3, u3), 0.f);
            split2(vA0, vA1, A2h[kt][0], A2l[kt][0]);
            split2(vB0, vB1, A2h[kt][1], A2l[kt][1]);
            split2(vA2, vA3, A2h[kt][2], A2l[kt][2]);
            split2(vB2, vB3, A2h[kt][3], A2l[kt][3]);
        }

        // ---- layer 2: z2 = H1 @ W1 (+b1 via col-50 feed), chain into A3 ----
        // nt=7 (cols 56..63) is all-zero: trimmed.
#pragma unroll
        for (int nt = 0; nt < 7; nt++) {
            float c0[4] = {0.f, 0.f, 0.f, 0.f};
            float c1[4] = {0.f, 0.f, 0.f, 0.f};
            const int rowoff = (nt * 8 + g) * WST + 2 * t4;
#pragma unroll
            for (int kt = 0; kt < 4; kt++) {
                const half* ph = Wt1hi + rowoff + kt * 16;
                const half* pl = Wt1lo + rowoff + kt * 16;
                uint32_t bh0 = *(const uint32_t*)ph;
                uint32_t bh1 = *(const uint32_t*)(ph + 8);
                uint32_t bl0 = *(const uint32_t*)pl;
                uint32_t bl1 = *(const uint32_t*)(pl + 8);
                float* cc = (kt < 2) ? c0 : c1;
                mma16816(cc, A2h[kt], bh0, bh1);
                mma16816(cc, A2h[kt], bl0, bl1);
                mma16816(cc, A2l[kt], bh0, bh1);
            }
            const int col0 = nt * 8 + 2 * t4;
            float v0 = (col0 == 50) ? 1.f : fmaxf(c0[0] + c1[0], 0.f);
            float v1 = fmaxf(c0[1] + c1[1], 0.f);             // odd col, never 50
            float v2 = (col0 == 50) ? 1.f : fmaxf(c0[2] + c1[2], 0.f);
            float v3 = fmaxf(c0[3] + c1[3], 0.f);
            const int kt2 = nt >> 1, s0 = (nt & 1) ? 2 : 0;
            split2(v0, v1, A3h[kt2][s0], A3l[kt2][s0]);
            split2(v2, v3, A3h[kt2][s0 + 1], A3l[kt2][s0 + 1]);
        }

        // ---- layer 3: z3 = H2 @ W2 (+b2), relu, accumulate over j ----
#pragma unroll
        for (int nt = 0; nt < 7; nt++) {
            float c0[4] = {0.f, 0.f, 0.f, 0.f};
            float c1[4] = {0.f, 0.f, 0.f, 0.f};
            const int rowoff = (nt * 8 + g) * WST + 2 * t4;
#pragma unroll
            for (int kt = 0; kt < 4; kt++) {
                const half* ph = Wt2hi + rowoff + kt * 16;
                const half* pl = Wt2lo + rowoff + kt * 16;
                uint32_t bh0 = *(const uint32_t*)ph;
                uint32_t bh1 = *(const uint32_t*)(ph + 8);
                uint32_t bl0 = *(const uint32_t*)pl;
                uint32_t bl1 = *(const uint32_t*)(pl + 8);
                float* cc = (kt < 2) ? c0 : c1;
                mma16816(cc, A3h[kt], bh0, bh1);
                mma16816(cc, A3h[kt], bl0, bl1);
                mma16816(cc, A3l[kt], bh0, bh1);
            }
            Fr[nt * 4 + 0] += fmaxf(c0[0] + c1[0], 0.f);
            Fr[nt * 4 + 1] += fmaxf(c0[1] + c1[1], 0.f);
            Fr[nt * 4 + 2] += fmaxf(c0[2] + c1[2], 0.f);
            Fr[nt * 4 + 3] += fmaxf(c0[3] + c1[3], 0.f);
        }
    }

    // ---- deterministic partial writeback (W3 folded post-sum in finalize) ----
    const int i0 = ib * 128 + w * 16 + g;
    const long base = (long)(m * 8 + jc) * NOBJ;
#pragma unroll
    for (int nt = 0; nt < 7; nt++) {
        const int col0 = nt * 8 + 2 * t4;
        if (col0 < 50) {
            g_partial[(base + i0) * 50 + col0]     = Fr[nt * 4 + 0];
            g_partial[(base + i0 + 8) * 50 + col0] = Fr[nt * 4 + 2];
        }
        if (col0 + 1 < 50) {
            g_partial[(base + i0) * 50 + col0 + 1]     = Fr[nt * 4 + 1];
            g_partial[(base + i0 + 8) * 50 + col0 + 1] = Fr[nt * 4 + 3];
        }
    }
}

// warp-per-(c,i) finalize: jc-reduce, fold W3, apply head MLP
__global__ void __launch_bounds__(256)
finalize_kernel(const float* __restrict__ gW3, const float* __restrict__ gb3,
                const float* __restrict__ aW0, const float* __restrict__ ab0,
                const float* __restrict__ aW1, const float* __restrict__ ab1,
                float* __restrict__ out)
{
    const int warp = blockIdx.x * (blockDim.x >> 5) + (threadIdx.x >> 5);
    const int lane = threadIdx.x & 31;

    if (warp >= 2048) return;
    const int c = warp >> 10;
    const int i = warp & 1023;

    float F[20];
#pragma unroll
    for (int o = 0; o < 20; o++) F[o] = 0.f;

    for (int idx = lane; idx < 200; idx += 32) {
        const int a = idx / 50, k = idx % 50;
        const int mm = a * 2 + c;
        const float* gp = g_partial + ((long)(mm * 8) * NOBJ + i) * 50 + k;
        float s = 0.f;
#pragma unroll
        for (int jcc = 0; jcc < 8; jcc++) s += gp[(long)jcc * NOBJ * 50];
        const float* w3 = gW3 + mm * 1000 + k * 20;
#pragma unroll
        for (int o = 0; o < 20; o++) F[o] = fmaf(s, w3[o], F[o]);
    }
#pragma unroll
    for (int off = 16; off; off >>= 1)
#pragma unroll
        for (int o = 0; o < 20; o++)
            F[o] += __shfl_xor_sync(0xffffffffu, F[o], off);
#pragma unroll
    for (int o = 0; o < 20; o++) {
        float b = gb3[(0 + c) * 20 + o] + gb3[(2 + c) * 20 + o]
                + gb3[(4 + c) * 20 + o] + gb3[(6 + c) * 20 + o];
        F[o] += 1024.f * b;
    }

    float p = 0.f;
    for (int l = lane; l < 50; l += 32) {
        float h = ab0[c * 50 + l];
#pragma unroll
        for (int o = 0; o < 20; o++)
            h = fmaf(F[o], aW0[c * 1000 + o * 50 + l], h);
        p = fmaf(fmaxf(h, 0.f), aW1[c * 50 + l], p);
    }
#pragma unroll
    for (int off = 16; off; off >>= 1)
        p += __shfl_xor_sync(0xffffffffu, p, off);
    if (lane == 0) out[c * 1024 + i] = p + ab1[c];
}

extern "C" void kernel_launch(void* const* d_in, const int* in_sizes, int n_in,
                              void* d_out, int out_size)
{
    const float* obj0  = (const float*)d_in[0];
    const float* obj1  = (const float*)d_in[1];
    const float* prev0 = (const float*)d_in[2];
    const float* prev1 = (const float*)d_in[3];
    const float* gW0   = (const float*)d_in[4];
    const float* gb0   = (const float*)d_in[5];
    const float* gW1   = (const float*)d_in[6];
    const float* gb1   = (const float*)d_in[7];
    const float* gW2   = (const float*)d_in[8];
    const float* gb2   = (const float*)d_in[9];
    const float* gW3   = (const float*)d_in[10];
    const float* gb3   = (const float*)d_in[11];
    const float* aW0   = (const float*)d_in[12];
    const float* ab0   = (const float*)d_in[13];
    const float* aW1   = (const float*)d_in[14];
    const float* ab1   = (const float*)d_in[15];

    dim3 grid(8, 8, 8);   // (module, i-block, j-chunk)
    pair_kernel<<<grid, TPB>>>(obj0, obj1, prev0, prev1,
                               gW0, gb0, gW1, gb1, gW2, gb2);
    finalize_kernel<<<256, 256>>>(gW3, gb3, aW0, ab0, aW1, ab1, (float*)d_out);
}

// round 5
// speedup vs baseline: 1.0791x; 1.0791x over previous
#include <cuda_runtime.h>
#include <cuda_fp16.h>
#include <cstdint>

#define NOBJ 1024
#define TPB  256
#define WST  72        // SMEM weight row stride (halfs): 144B -> conflict-free

// partial[m][jc][i][50]  (fully overwritten every launch by the 512 CTAs)
__device__ float g_partial[8 * 8 * NOBJ * 50];

// ---------------------------------------------------------------------------
// mma.m16n8k16 row.col f32.f16.f16.f32
// A frag (4 b32): a0=(row g, k=2t4,2t4+1) a1=(g+8, same) a2=(g, +8) a3=(g+8, +8)
// B frag (2 b32): b0=(k=2t4,2t4+1, n=g)   b1=(k=+8, n=g)
// C frag (4 f32): c0=(g, n=2t4) c1=(g, 2t4+1) c2=(g+8, 2t4) c3=(g+8, 2t4+1)
// ---------------------------------------------------------------------------
__device__ __forceinline__ void mma16816(float c[4], const uint32_t a[4],
                                         uint32_t b0, uint32_t b1)
{
    asm("mma.sync.aligned.m16n8k16.row.col.f32.f16.f16.f32 "
        "{%0,%1,%2,%3}, {%4,%5,%6,%7}, {%8,%9}, {%0,%1,%2,%3};\n"
        : "+f"(c[0]), "+f"(c[1]), "+f"(c[2]), "+f"(c[3])
        : "r"(a[0]), "r"(a[1]), "r"(a[2]), "r"(a[3]), "r"(b0), "r"(b1));
}

// split (x,y) into fp16 hi pair + fp16 lo (residual) pair, packed as b32
__device__ __forceinline__ void split2(float x, float y, uint32_t& hi, uint32_t& lo)
{
    half2 h = __floats2half2_rn(x, y);
    float2 f = __half22float2(h);
    half2 l = __floats2half2_rn(x - f.x, y - f.y);
    hi = *reinterpret_cast<uint32_t*>(&h);
    lo = *reinterpret_cast<uint32_t*>(&l);
}

__device__ __forceinline__ void split_w(float v, half& hi, half& lo)
{
    hi = __float2half_rn(v);
    lo = __float2half_rn(v - __half2float(hi));
}

__global__ void __launch_bounds__(TPB, 1)
pair_kernel(const float* __restrict__ obj0, const float* __restrict__ obj1,
            const float* __restrict__ prev0, const float* __restrict__ prev1,
            const float* __restrict__ gW0, const float* __restrict__ gb0,
            const float* __restrict__ gW1, const float* __restrict__ gb1,
            const float* __restrict__ gW2, const float* __restrict__ gb2)
{
    const int m  = blockIdx.x;   // module (actor class = m>>1, actee class = m&1)
    const int ib = blockIdx.y;   // i-block (128 actees)
    const int jc = blockIdx.z;   // j-chunk (128 actors)
    const int t  = threadIdx.x;
    const int w  = t >> 5;
    const int lane = t & 31;
    const int t4 = lane & 3;
    const int g  = lane >> 2;

    const int ac = m >> 1;
    const float* actor = (ac == 0) ? obj0 : (ac == 1) ? obj1 : (ac == 2) ? prev0 : prev1;
    const float* actee = (m & 1) ? obj1 : obj0;

    // Transposed, padded weights: Wt[n][k] = W[k][n]; row 50 of W carries bias.
    __shared__ half Wt1hi[64 * WST], Wt1lo[64 * WST];
    __shared__ half Wt2hi[64 * WST], Wt2lo[64 * WST];
    __shared__ float alph[128];
    __shared__ float p_[64], q_[64], r_[64];   // layer-1 rank-1 constants (fp32)

    for (int x = t; x < 64 * WST; x += TPB) {
        Wt1hi[x] = __float2half(0.f);  Wt1lo[x] = __float2half(0.f);
        Wt2hi[x] = __float2half(0.f);  Wt2lo[x] = __float2half(0.f);
    }
    if (t < 64) {
        p_[t] = (t < 50) ? gW0[m * 100 + t]      : 0.f;     // W0[m][0][t]
        q_[t] = (t < 50) ? gW0[m * 100 + 50 + t] : 0.f;     // W0[m][1][t]
        r_[t] = (t < 50) ? gb0[m * 50 + t] : (t == 50 ? 1.f : 0.f);  // bias-feed col
    }
    if (t < 128) alph[t] = actor[jc * 128 + t];
    __syncthreads();
    for (int x = t; x < 51 * 50; x += TPB) {
        int k = x / 50, n = x % 50;
        float w1 = (k < 50) ? gW1[m * 2500 + k * 50 + n] : gb1[m * 50 + n];
        float w2 = (k < 50) ? gW2[m * 2500 + k * 50 + n] : gb2[m * 50 + n];
        half hi, lo;
        split_w(w1, hi, lo);  Wt1hi[n * WST + k] = hi;  Wt1lo[n * WST + k] = lo;
        split_w(w2, hi, lo);  Wt2hi[n * WST + k] = hi;  Wt2lo[n * WST + k] = lo;
    }

    const float betaA = actee[ib * 128 + w * 16 + g];
    const float betaB = actee[ib * 128 + w * 16 + g + 8];

    float Fr[28];
#pragma unroll
    for (int x = 0; x < 28; x++) Fr[x] = 0.f;

    // A3 kt=3 upper slots (k=56..63) are always zero (nt=7 trimmed away)
    uint32_t A3h[2][4][4], A3l[2][4][4];
#pragma unroll
    for (int jx = 0; jx < 2; jx++) {
        A3h[jx][3][2] = A3h[jx][3][3] = 0u;
        A3l[jx][3][2] = A3l[jx][3][3] = 0u;
    }

    __syncthreads();    // the ONLY barrier before the writeback

    // two actors per iteration: 4 independent HMMA chains per warp
    for (int jj = 0; jj < 128; jj += 2) {

        // ---- layer 1 (rank-1 collapse) -> A fragments, all in registers ----
        uint32_t A2h[2][4][4], A2l[2][4][4];
#pragma unroll
        for (int jx = 0; jx < 2; jx++) {
            const float al = alph[jj + jx];
#pragma unroll
            for (int kt = 0; kt < 4; kt++) {
                const int c0i = kt * 16 + 2 * t4;   // cols c, c+1, c+8, c+9
                float u0 = fmaf(al, p_[c0i],     r_[c0i]);
                float u1 = fmaf(al, p_[c0i + 1], r_[c0i + 1]);
                float u2 = fmaf(al, p_[c0i + 8], r_[c0i + 8]);
                float u3 = fmaf(al, p_[c0i + 9], r_[c0i + 9]);
                float q0 = q_[c0i], q1 = q_[c0i + 1];
                float q2 = q_[c0i + 8], q3 = q_[c0i + 9];
                float vA0 = fmaxf(fmaf(betaA, q0, u0), 0.f);
                float vA1 = fmaxf(fmaf(betaA, q1, u1), 0.f);
                float vA2 = fmaxf(fmaf(betaA, q2, u2), 0.f);
                float vA3 = fmaxf(fmaf(betaA, q3, u3), 0.f);
                float vB0 = fmaxf(fmaf(betaB, q0, u0), 0.f);
                float vB1 = fmaxf(fmaf(betaB, q1, u1), 0.f);
                float vB2 = fmaxf(fmaf(betaB, q2, u2), 0.f);
                float vB3 = fmaxf(fmaf(betaB, q3, u3), 0.f);
                split2(vA0, vA1, A2h[jx][kt][0], A2l[jx][kt][0]);
                split2(vB0, vB1, A2h[jx][kt][1], A2l[jx][kt][1]);
                split2(vA2, vA3, A2h[jx][kt][2], A2l[jx][kt][2]);
                split2(vB2, vB3, A2h[jx][kt][3], A2l[jx][kt][3]);
            }
        }

        // ---- layer 2: z2 = H1 @ W1 (+b1 via col-50 feed), chain into A3 ----
        // nt=7 (cols 56..63) all-zero: trimmed. B frags shared by both j's.
#pragma unroll
        for (int nt = 0; nt < 7; nt++) {
            float c0[2][4] = {{0.f,0.f,0.f,0.f},{0.f,0.f,0.f,0.f}};
            float c1[2][4] = {{0.f,0.f,0.f,0.f},{0.f,0.f,0.f,0.f}};
            const int rowoff = (nt * 8 + g) * WST + 2 * t4;
#pragma unroll
            for (int kt = 0; kt < 4; kt++) {
                const half* ph = Wt1hi + rowoff + kt * 16;
                const half* pl = Wt1lo + rowoff + kt * 16;
                uint32_t bh0 = *(const uint32_t*)ph;
                uint32_t bh1 = *(const uint32_t*)(ph + 8);
                uint32_t bl0 = *(const uint32_t*)pl;
                uint32_t bl1 = *(const uint32_t*)(pl + 8);
#pragma unroll
                for (int jx = 0; jx < 2; jx++) {
                    float* cc = (kt < 2) ? c0[jx] : c1[jx];
                    mma16816(cc, A2h[jx][kt], bh0, bh1);
                    mma16816(cc, A2h[jx][kt], bl0, bl1);
                    mma16816(cc, A2l[jx][kt], bh0, bh1);
                }
            }
            const int col0 = nt * 8 + 2 * t4;
            const int kt2 = nt >> 1, s0 = (nt & 1) ? 2 : 0;
#pragma unroll
            for (int jx = 0; jx < 2; jx++) {
                float v0 = (col0 == 50) ? 1.f : fmaxf(c0[jx][0] + c1[jx][0], 0.f);
                float v1 = fmaxf(c0[jx][1] + c1[jx][1], 0.f);   // odd col, never 50
                float v2 = (col0 == 50) ? 1.f : fmaxf(c0[jx][2] + c1[jx][2], 0.f);
                float v3 = fmaxf(c0[jx][3] + c1[jx][3], 0.f);
                split2(v0, v1, A3h[jx][kt2][s0],     A3l[jx][kt2][s0]);
                split2(v2, v3, A3h[jx][kt2][s0 + 1], A3l[jx][kt2][s0 + 1]);
            }
        }

        // ---- layer 3: z3 = H2 @ W2 (+b2), relu, accumulate over j ----
#pragma unroll
        for (int nt = 0; nt < 7; nt++) {
            float c0[2][4] = {{0.f,0.f,0.f,0.f},{0.f,0.f,0.f,0.f}};
            float c1[2][4] = {{0.f,0.f,0.f,0.f},{0.f,0.f,0.f,0.f}};
            const int rowoff = (nt * 8 + g) * WST + 2 * t4;
#pragma unroll
            for (int kt = 0; kt < 4; kt++) {
                const half* ph = Wt2hi + rowoff + kt * 16;
                const half* pl = Wt2lo + rowoff + kt * 16;
                uint32_t bh0 = *(const uint32_t*)ph;
                uint32_t bh1 = *(const uint32_t*)(ph + 8);
                uint32_t bl0 = *(const uint32_t*)pl;
                uint32_t bl1 = *(const uint32_t*)(pl + 8);
#pragma unroll
                for (int jx = 0; jx < 2; jx++) {
                    float* cc = (kt < 2) ? c0[jx] : c1[jx];
                    mma16816(cc, A3h[jx][kt], bh0, bh1);
                    mma16816(cc, A3h[jx][kt], bl0, bl1);
                    mma16816(cc, A3l[jx][kt], bh0, bh1);
                }
            }
#pragma unroll
            for (int jx = 0; jx < 2; jx++) {
                Fr[nt * 4 + 0] += fmaxf(c0[jx][0] + c1[jx][0], 0.f);
                Fr[nt * 4 + 1] += fmaxf(c0[jx][1] + c1[jx][1], 0.f);
                Fr[nt * 4 + 2] += fmaxf(c0[jx][2] + c1[jx][2], 0.f);
                Fr[nt * 4 + 3] += fmaxf(c0[jx][3] + c1[jx][3], 0.f);
            }
        }
    }

    // ---- deterministic partial writeback (W3 folded post-sum in finalize) ----
    const int i0 = ib * 128 + w * 16 + g;
    const long base = (long)(m * 8 + jc) * NOBJ;
#pragma unroll
    for (int nt = 0; nt < 7; nt++) {
        const int col0 = nt * 8 + 2 * t4;
        if (col0 < 50) {
            g_partial[(base + i0) * 50 + col0]     = Fr[nt * 4 + 0];
            g_partial[(base + i0 + 8) * 50 + col0] = Fr[nt * 4 + 2];
        }
        if (col0 + 1 < 50) {
            g_partial[(base + i0) * 50 + col0 + 1]     = Fr[nt * 4 + 1];
            g_partial[(base + i0 + 8) * 50 + col0 + 1] = Fr[nt * 4 + 3];
        }
    }
}

// warp-per-(c,i) finalize: jc-reduce, fold W3, apply head MLP
__global__ void __launch_bounds__(256)
finalize_kernel(const float* __restrict__ gW3, const float* __restrict__ gb3,
                const float* __restrict__ aW0, const float* __restrict__ ab0,
                const float* __restrict__ aW1, const float* __restrict__ ab1,
                float* __restrict__ out)
{
    const int warp = blockIdx.x * (blockDim.x >> 5) + (threadIdx.x >> 5);
    const int lane = threadIdx.x & 31;

    if (warp >= 2048) return;
    const int c = warp >> 10;
    const int i = warp & 1023;

    float F[20];
#pragma unroll
    for (int o = 0; o < 20; o++) F[o] = 0.f;

    for (int idx = lane; idx < 200; idx += 32) {
        const int a = idx / 50, k = idx % 50;
        const int mm = a * 2 + c;
        const float* gp = g_partial + ((long)(mm * 8) * NOBJ + i) * 50 + k;
        float s = 0.f;
#pragma unroll
        for (int jcc = 0; jcc < 8; jcc++) s += gp[(long)jcc * NOBJ * 50];
        const float* w3 = gW3 + mm * 1000 + k * 20;
#pragma unroll
        for (int o = 0; o < 20; o++) F[o] = fmaf(s, w3[o], F[o]);
    }
#pragma unroll
    for (int off = 16; off; off >>= 1)
#pragma unroll
        for (int o = 0; o < 20; o++)
            F[o] += __shfl_xor_sync(0xffffffffu, F[o], off);
#pragma unroll
    for (int o = 0; o < 20; o++) {
        float b = gb3[(0 + c) * 20 + o] + gb3[(2 + c) * 20 + o]
                + gb3[(4 + c) * 20 + o] + gb3[(6 + c) * 20 + o];
        F[o] += 1024.f * b;
    }

    float p = 0.f;
    for (int l = lane; l < 50; l += 32) {
        float h = ab0[c * 50 + l];
#pragma unroll
        for (int o = 0; o < 20; o++)
            h = fmaf(F[o], aW0[c * 1000 + o * 50 + l], h);
        p = fmaf(fmaxf(h, 0.f), aW1[c * 50 + l], p);
    }
#pragma unroll
    for (int off = 16; off; off >>= 1)
        p += __shfl_xor_sync(0xffffffffu, p, off);
    if (lane == 0) out[c * 1024 + i] = p + ab1[c];
}

extern "C" void kernel_launch(void* const* d_in, const int* in_sizes, int n_in,
                              void* d_out, int out_size)
{
    const float* obj0  = (const float*)d_in[0];
    const float* obj1  = (const float*)d_in[1];
    const float* prev0 = (const float*)d_in[2];
    const float* prev1 = (const float*)d_in[3];
    const float* gW0   = (const float*)d_in[4];
    const float* gb0   = (const float*)d_in[5];
    const float* gW1   = (const float*)d_in[6];
    const float* gb1   = (const float*)d_in[7];
    const float* gW2   = (const float*)d_in[8];
    const float* gb2   = (const float*)d_in[9];
    const float* gW3   = (const float*)d_in[10];
    const float* gb3   = (const float*)d_in[11];
    const float* aW0   = (const float*)d_in[12];
    const float* ab0   = (const float*)d_in[13];
    const float* aW1   = (const float*)d_in[14];
    const float* ab1   = (const float*)d_in[15];

    dim3 grid(8, 8, 8);   // (module, i-block, j-chunk)
    pair_kernel<<<grid, TPB>>>(obj0, obj1, prev0, prev1,
                               gW0, gb0, gW1, gb1, gW2, gb2);
    finalize_kernel<<<256, 256>>>(gW3, gb3, aW0, ab0, aW1, ab1, (float*)d_out);
}

// round 6
// speedup vs baseline: 1.3563x; 1.2568x over previous
#include <cuda_runtime.h>
#include <cuda_fp16.h>
#include <cstdint>

#define NOBJ 1024
#define TPB  256
#define WST  72        // SMEM weight row stride (halfs): 144B -> conflict-free

// partial[m][jc][i][50]  (fully overwritten every launch by the 512 CTAs)
__device__ float g_partial[8 * 8 * NOBJ * 50];

// ---------------------------------------------------------------------------
// mma.m16n8k16 row.col f32.f16.f16.f32
// A frag (4 b32): a0=(row g, k=2t4,2t4+1) a1=(g+8, same) a2=(g, +8) a3=(g+8, +8)
// B frag (2 b32): b0=(k=2t4,2t4+1, n=g)   b1=(k=+8, n=g)
// C frag (4 f32): c0=(g, n=2t4) c1=(g, 2t4+1) c2=(g+8, 2t4) c3=(g+8, 2t4+1)
// ---------------------------------------------------------------------------
__device__ __forceinline__ void mma16816(float c[4], const uint32_t a[4],
                                         uint32_t b0, uint32_t b1)
{
    asm("mma.sync.aligned.m16n8k16.row.col.f32.f16.f16.f32 "
        "{%0,%1,%2,%3}, {%4,%5,%6,%7}, {%8,%9}, {%0,%1,%2,%3};\n"
        : "+f"(c[0]), "+f"(c[1]), "+f"(c[2]), "+f"(c[3])
        : "r"(a[0]), "r"(a[1]), "r"(a[2]), "r"(a[3]), "r"(b0), "r"(b1));
}

// split (x,y) into fp16 hi pair + fp16 lo (residual) pair, packed as b32
__device__ __forceinline__ void split2(float x, float y, uint32_t& hi, uint32_t& lo)
{
    half2 h = __floats2half2_rn(x, y);
    float2 f = __half22float2(h);
    half2 l = __floats2half2_rn(x - f.x, y - f.y);
    hi = *reinterpret_cast<uint32_t*>(&h);
    lo = *reinterpret_cast<uint32_t*>(&l);
}

__device__ __forceinline__ void split_w(float v, half& hi, half& lo)
{
    hi = __float2half_rn(v);
    lo = __float2half_rn(v - __half2float(hi));
}

__global__ void __launch_bounds__(TPB, 1)
pair_kernel(const float* __restrict__ obj0, const float* __restrict__ obj1,
            const float* __restrict__ prev0, const float* __restrict__ prev1,
            const float* __restrict__ gW0, const float* __restrict__ gb0,
            const float* __restrict__ gW1, const float* __restrict__ gb1,
            const float* __restrict__ gW2, const float* __restrict__ gb2)
{
    const int m  = blockIdx.x;   // module (actor class = m>>1, actee class = m&1)
    const int ib = blockIdx.y;   // i-block (128 actees)
    const int jc = blockIdx.z;   // j-chunk (128 actors)
    const int t  = threadIdx.x;
    const int w  = t >> 5;
    const int lane = t & 31;
    const int t4 = lane & 3;
    const int g  = lane >> 2;

    const int ac = m >> 1;
    const float* actor = (ac == 0) ? obj0 : (ac == 1) ? obj1 : (ac == 2) ? prev0 : prev1;
    const float* actee = (m & 1) ? obj1 : obj0;

    // Transposed, padded weights: Wt[n][k] = W[k][n]; row 50 of W carries bias.
    __shared__ half Wt1hi[64 * WST], Wt1lo[64 * WST];
    __shared__ half Wt2hi[64 * WST], Wt2lo[64 * WST];
    __shared__ float alph[128];

    for (int x = t; x < 64 * WST; x += TPB) {
        Wt1hi[x] = __float2half(0.f);  Wt1lo[x] = __float2half(0.f);
        Wt2hi[x] = __float2half(0.f);  Wt2lo[x] = __float2half(0.f);
    }
    __syncthreads();
    for (int x = t; x < 51 * 50; x += TPB) {
        int k = x / 50, n = x % 50;
        float w1 = (k < 50) ? gW1[m * 2500 + k * 50 + n] : gb1[m * 50 + n];
        float w2 = (k < 50) ? gW2[m * 2500 + k * 50 + n] : gb2[m * 50 + n];
        half hi, lo;
        split_w(w1, hi, lo);  Wt1hi[n * WST + k] = hi;  Wt1lo[n * WST + k] = lo;
        split_w(w2, hi, lo);  Wt2hi[n * WST + k] = hi;  Wt2lo[n * WST + k] = lo;
    }
    if (t < 128) alph[t] = actor[jc * 128 + t];

    // per-thread layer-1 constants at this thread's 16 fragment columns
    float pc[16], qc[16], rc[16];
#pragma unroll
    for (int kt = 0; kt < 4; kt++)
#pragma unroll
        for (int s = 0; s < 4; s++) {
            int col = kt * 16 + 2 * t4 + ((s >> 1) << 3) + (s & 1);
            int idx = kt * 4 + s;
            pc[idx] = (col < 50) ? gW0[m * 100 + col] : 0.f;        // W0[m][0][col]
            qc[idx] = (col < 50) ? gW0[m * 100 + 50 + col] : 0.f;   // W0[m][1][col]
            rc[idx] = (col < 50) ? gb0[m * 50 + col]
                                 : (col == 50 ? 1.f : 0.f);          // bias-feed col
        }
    const float betaA = actee[ib * 128 + w * 16 + g];
    const float betaB = actee[ib * 128 + w * 16 + g + 8];

    float Fr[28];
#pragma unroll
    for (int x = 0; x < 28; x++) Fr[x] = 0.f;

    // A3 kt=3 upper slots (k=56..63) always zero: nt=7 trimmed away
    uint32_t A3h[4][4], A3l[4][4];
    A3h[3][2] = A3h[3][3] = A3l[3][2] = A3l[3][3] = 0u;

    __syncthreads();    // the ONLY barrier before the writeback

    for (int jj = 0; jj < 128; ++jj) {
        const float al = alph[jj];

        // ---- layer 1 (rank-1 collapse) -> A fragments, all in registers ----
        uint32_t A2h[4][4], A2l[4][4];
#pragma unroll
        for (int kt = 0; kt < 4; kt++) {
            const int b = kt * 4;
            float u0 = fmaf(al, pc[b + 0], rc[b + 0]);
            float u1 = fmaf(al, pc[b + 1], rc[b + 1]);
            float u2 = fmaf(al, pc[b + 2], rc[b + 2]);
            float u3 = fmaf(al, pc[b + 3], rc[b + 3]);
            float vA0 = fmaxf(fmaf(betaA, qc[b + 0], u0), 0.f);
            float vA1 = fmaxf(fmaf(betaA, qc[b + 1], u1), 0.f);
            float vA2 = fmaxf(fmaf(betaA, qc[b + 2], u2), 0.f);
            float vA3 = fmaxf(fmaf(betaA, qc[b + 3], u3), 0.f);
            float vB0 = fmaxf(fmaf(betaB, qc[b + 0], u0), 0.f);
            float vB1 = fmaxf(fmaf(betaB, qc[b + 1], u1), 0.f);
            float vB2 = fmaxf(fmaf(betaB, qc[b + 2], u2), 0.f);
            float vB3 = fmaxf(fmaf(betaB, qc[b + 3], u3), 0.f);
            split2(vA0, vA1, A2h[kt][0], A2l[kt][0]);
            split2(vB0, vB1, A2h[kt][1], A2l[kt][1]);
            split2(vA2, vA3, A2h[kt][2], A2l[kt][2]);
            split2(vB2, vB3, A2h[kt][3], A2l[kt][3]);
        }

        // ---- layer 2: z2 = H1 @ W1 (+b1 via col-50 feed), chain into A3 ----
        // nt = 0..6 (cols 56..63 all-zero). Two n-tiles in flight -> 4 chains.
#pragma unroll
        for (int np = 0; np < 4; np++) {
            const int ntA = 2 * np, ntB = 2 * np + 1;   // ntB==7 disabled at np=3
            float cA0[4] = {0.f,0.f,0.f,0.f}, cA1[4] = {0.f,0.f,0.f,0.f};
            float cB0[4] = {0.f,0.f,0.f,0.f}, cB1[4] = {0.f,0.f,0.f,0.f};
            const int roA = (ntA * 8 + g) * WST + 2 * t4;
            const int roB = (ntB * 8 + g) * WST + 2 * t4;
#pragma unroll
            for (int kt = 0; kt < 4; kt++) {
                const half* phA = Wt1hi + roA + kt * 16;
                const half* plA = Wt1lo + roA + kt * 16;
                uint32_t bhA0 = *(const uint32_t*)phA;
                uint32_t bhA1 = *(const uint32_t*)(phA + 8);
                uint32_t blA0 = *(const uint32_t*)plA;
                uint32_t blA1 = *(const uint32_t*)(plA + 8);
                float* ccA = (kt < 2) ? cA0 : cA1;
                mma16816(ccA, A2h[kt], bhA0, bhA1);
                mma16816(ccA, A2h[kt], blA0, blA1);
                mma16816(ccA, A2l[kt], bhA0, bhA1);
                if (np < 3) {
                    const half* phB = Wt1hi + roB + kt * 16;
                    const half* plB = Wt1lo + roB + kt * 16;
                    uint32_t bhB0 = *(const uint32_t*)phB;
                    uint32_t bhB1 = *(const uint32_t*)(phB + 8);
                    uint32_t blB0 = *(const uint32_t*)plB;
                    uint32_t blB1 = *(const uint32_t*)(plB + 8);
                    float* ccB = (kt < 2) ? cB0 : cB1;
                    mma16816(ccB, A2h[kt], bhB0, bhB1);
                    mma16816(ccB, A2h[kt], blB0, blB1);
                    mma16816(ccB, A2l[kt], bhB0, bhB1);
                }
            }
            {
                const int col0 = ntA * 8 + 2 * t4;
                float v0 = (col0 == 50) ? 1.f : fmaxf(cA0[0] + cA1[0], 0.f);
                float v1 = fmaxf(cA0[1] + cA1[1], 0.f);       // odd col, never 50
                float v2 = (col0 == 50) ? 1.f : fmaxf(cA0[2] + cA1[2], 0.f);
                float v3 = fmaxf(cA0[3] + cA1[3], 0.f);
                const int kt2 = ntA >> 1, s0 = (ntA & 1) ? 2 : 0;
                split2(v0, v1, A3h[kt2][s0],     A3l[kt2][s0]);
                split2(v2, v3, A3h[kt2][s0 + 1], A3l[kt2][s0 + 1]);
            }
            if (np < 3) {
                const int col0 = ntB * 8 + 2 * t4;
                float v0 = (col0 == 50) ? 1.f : fmaxf(cB0[0] + cB1[0], 0.f);
                float v1 = fmaxf(cB0[1] + cB1[1], 0.f);
                float v2 = (col0 == 50) ? 1.f : fmaxf(cB0[2] + cB1[2], 0.f);
                float v3 = fmaxf(cB0[3] + cB1[3], 0.f);
                const int kt2 = ntB >> 1, s0 = (ntB & 1) ? 2 : 0;
                split2(v0, v1, A3h[kt2][s0],     A3l[kt2][s0]);
                split2(v2, v3, A3h[kt2][s0 + 1], A3l[kt2][s0 + 1]);
            }
        }

        // ---- layer 3: z3 = H2 @ W2 (+b2), relu, accumulate over j ----
#pragma unroll
        for (int np = 0; np < 4; np++) {
            const int ntA = 2 * np, ntB = 2 * np + 1;
            float cA0[4] = {0.f,0.f,0.f,0.f}, cA1[4] = {0.f,0.f,0.f,0.f};
            float cB0[4] = {0.f,0.f,0.f,0.f}, cB1[4] = {0.f,0.f,0.f,0.f};
            const int roA = (ntA * 8 + g) * WST + 2 * t4;
            const int roB = (ntB * 8 + g) * WST + 2 * t4;
#pragma unroll
            for (int kt = 0; kt < 4; kt++) {
                const half* phA = Wt2hi + roA + kt * 16;
                const half* plA = Wt2lo + roA + kt * 16;
                uint32_t bhA0 = *(const uint32_t*)phA;
                uint32_t bhA1 = *(const uint32_t*)(phA + 8);
                uint32_t blA0 = *(const uint32_t*)plA;
                uint32_t blA1 = *(const uint32_t*)(plA + 8);
                float* ccA = (kt < 2) ? cA0 : cA1;
                mma16816(ccA, A3h[kt], bhA0, bhA1);
                mma16816(ccA, A3h[kt], blA0, blA1);
                mma16816(ccA, A3l[kt], bhA0, bhA1);
                if (np < 3) {
                    const half* phB = Wt2hi + roB + kt * 16;
                    const half* plB = Wt2lo + roB + kt * 16;
                    uint32_t bhB0 = *(const uint32_t*)phB;
                    uint32_t bhB1 = *(const uint32_t*)(phB + 8);
                    uint32_t blB0 = *(const uint32_t*)plB;
                    uint32_t blB1 = *(const uint32_t*)(plB + 8);
                    float* ccB = (kt < 2) ? cB0 : cB1;
                    mma16816(ccB, A3h[kt], bhB0, bhB1);
                    mma16816(ccB, A3h[kt], blB0, blB1);
                    mma16816(ccB, A3l[kt], bhB0, bhB1);
                }
            }
            Fr[ntA * 4 + 0] += fmaxf(cA0[0] + cA1[0], 0.f);
            Fr[ntA * 4 + 1] += fmaxf(cA0[1] + cA1[1], 0.f);
            Fr[ntA * 4 + 2] += fmaxf(cA0[2] + cA1[2], 0.f);
            Fr[ntA * 4 + 3] += fmaxf(cA0[3] + cA1[3], 0.f);
            if (np < 3) {
                Fr[ntB * 4 + 0] += fmaxf(cB0[0] + cB1[0], 0.f);
                Fr[ntB * 4 + 1] += fmaxf(cB0[1] + cB1[1], 0.f);
                Fr[ntB * 4 + 2] += fmaxf(cB0[2] + cB1[2], 0.f);
                Fr[ntB * 4 + 3] += fmaxf(cB0[3] + cB1[3], 0.f);
            }
        }
    }

    // ---- deterministic partial writeback (W3 folded post-sum in finalize) ----
    const int i0 = ib * 128 + w * 16 + g;
    const long base = (long)(m * 8 + jc) * NOBJ;
#pragma unroll
    for (int nt = 0; nt < 7; nt++) {
        const int col0 = nt * 8 + 2 * t4;
        if (col0 < 50) {
            g_partial[(base + i0) * 50 + col0]     = Fr[nt * 4 + 0];
            g_partial[(base + i0 + 8) * 50 + col0] = Fr[nt * 4 + 2];
        }
        if (col0 + 1 < 50) {
            g_partial[(base + i0) * 50 + col0 + 1]     = Fr[nt * 4 + 1];
            g_partial[(base + i0 + 8) * 50 + col0 + 1] = Fr[nt * 4 + 3];
        }
    }
}

// warp-per-(c,i) finalize: jc-reduce, fold W3, apply head MLP
__global__ void __launch_bounds__(256)
finalize_kernel(const float* __restrict__ gW3, const float* __restrict__ gb3,
                const float* __restrict__ aW0, const float* __restrict__ ab0,
                const float* __restrict__ aW1, const float* __restrict__ ab1,
                float* __restrict__ out)
{
    const int warp = blockIdx.x * (blockDim.x >> 5) + (threadIdx.x >> 5);
    const int lane = threadIdx.x & 31;

    if (warp >= 2048) return;
    const int c = warp >> 10;
    const int i = warp & 1023;

    float F[20];
#pragma unroll
    for (int o = 0; o < 20; o++) F[o] = 0.f;

    for (int idx = lane; idx < 200; idx += 32) {
        const int a = idx / 50, k = idx % 50;
        const int mm = a * 2 + c;
        const float* gp = g_partial + ((long)(mm * 8) * NOBJ + i) * 50 + k;
        float s = 0.f;
#pragma unroll
        for (int jcc = 0; jcc < 8; jcc++) s += gp[(long)jcc * NOBJ * 50];
        const float* w3 = gW3 + mm * 1000 + k * 20;
#pragma unroll
        for (int o = 0; o < 20; o++) F[o] = fmaf(s, w3[o], F[o]);
    }
#pragma unroll
    for (int off = 16; off; off >>= 1)
#pragma unroll
        for (int o = 0; o < 20; o++)
            F[o] += __shfl_xor_sync(0xffffffffu, F[o], off);
#pragma unroll
    for (int o = 0; o < 20; o++) {
        float b = gb3[(0 + c) * 20 + o] + gb3[(2 + c) * 20 + o]
                + gb3[(4 + c) * 20 + o] + gb3[(6 + c) * 20 + o];
        F[o] += 1024.f * b;
    }

    float p = 0.f;
    for (int l = lane; l < 50; l += 32) {
        float h = ab0[c * 50 + l];
#pragma unroll
        for (int o = 0; o < 20; o++)
            h = fmaf(F[o], aW0[c * 1000 + o * 50 + l], h);
        p = fmaf(fmaxf(h, 0.f), aW1[c * 50 + l], p);
    }
#pragma unroll
    for (int off = 16; off; off >>= 1)
        p += __shfl_xor_sync(0xffffffffu, p, off);
    if (lane == 0) out[c * 1024 + i] = p + ab1[c];
}

extern "C" void kernel_launch(void* const* d_in, const int* in_sizes, int n_in,
                              void* d_out, int out_size)
{
    const float* obj0  = (const float*)d_in[0];
    const float* obj1  = (const float*)d_in[1];
    const float* prev0 = (const float*)d_in[2];
    const float* prev1 = (const float*)d_in[3];
    const float* gW0   = (const float*)d_in[4];
    const float* gb0   = (const float*)d_in[5];
    const float* gW1   = (const float*)d_in[6];
    const float* gb1   = (const float*)d_in[7];
    const float* gW2   = (const float*)d_in[8];
    const float* gb2   = (const float*)d_in[9];
    const float* gW3   = (const float*)d_in[10];
    const float* gb3   = (const float*)d_in[11];
    const float* aW0   = (const float*)d_in[12];
    const float* ab0   = (const float*)d_in[13];
    const float* aW1   = (const float*)d_in[14];
    const float* ab1   = (const float*)d_in[15];

    dim3 grid(8, 8, 8);   // (module, i-block, j-chunk)
    pair_kernel<<<grid, TPB>>>(obj0, obj1, prev0, prev1,
                               gW0, gb0, gW1, gb1, gW2, gb2);
    finalize_kernel<<<256, 256>>>(gW3, gb3, aW0, ab0, aW1, ab1, (float*)d_out);
}

// round 7
// speedup vs baseline: 1.8605x; 1.3718x over previous
#include <cuda_runtime.h>
#include <cuda_fp16.h>
#include <cstdint>

#define NOBJ 1024
#define TPB  256
#define WST  72        // SMEM weight row stride (halfs): 144B -> conflict-free

// partial[m][jc][i][50]  (fully overwritten every launch by the 512 CTAs)
__device__ float g_partial[8 * 8 * NOBJ * 50];

// ---------------------------------------------------------------------------
// mma.m16n8k16 row.col f32.f16.f16.f32
// A frag (4 b32): a0=(row g, k=2t4,2t4+1) a1=(g+8, same) a2=(g, +8) a3=(g+8, +8)
// B frag (2 b32): b0=(k=2t4,2t4+1, n=g)   b1=(k=+8, n=g)
// C frag (4 f32): c0=(g, n=2t4) c1=(g, 2t4+1) c2=(g+8, 2t4) c3=(g+8, 2t4+1)
// ---------------------------------------------------------------------------
__device__ __forceinline__ void mma16816(float c[4], const uint32_t a[4],
                                         uint32_t b0, uint32_t b1)
{
    asm("mma.sync.aligned.m16n8k16.row.col.f32.f16.f16.f32 "
        "{%0,%1,%2,%3}, {%4,%5,%6,%7}, {%8,%9}, {%0,%1,%2,%3};\n"
        : "+f"(c[0]), "+f"(c[1]), "+f"(c[2]), "+f"(c[3])
        : "r"(a[0]), "r"(a[1]), "r"(a[2]), "r"(a[3]), "r"(b0), "r"(b1));
}

__device__ __forceinline__ uint32_t pack2(float x, float y)
{
    half2 h = __floats2half2_rn(x, y);
    return *reinterpret_cast<uint32_t*>(&h);
}

__device__ __forceinline__ void split_w(float v, half& hi, half& lo)
{
    hi = __float2half_rn(v);
    lo = __float2half_rn(v - __half2float(hi));
}

__global__ void __launch_bounds__(TPB, 1)
pair_kernel(const float* __restrict__ obj0, const float* __restrict__ obj1,
            const float* __restrict__ prev0, const float* __restrict__ prev1,
            const float* __restrict__ gW0, const float* __restrict__ gb0,
            const float* __restrict__ gW1, const float* __restrict__ gb1,
            const float* __restrict__ gW2, const float* __restrict__ gb2)
{
    const int m  = blockIdx.x;   // module (actor class = m>>1, actee class = m&1)
    const int ib = blockIdx.y;   // i-block (128 actees)
    const int jc = blockIdx.z;   // j-chunk (128 actors)
    const int t  = threadIdx.x;
    const int w  = t >> 5;
    const int lane = t & 31;
    const int t4 = lane & 3;
    const int g  = lane >> 2;

    const int ac = m >> 1;
    const float* actor = (ac == 0) ? obj0 : (ac == 1) ? obj1 : (ac == 2) ? prev0 : prev1;
    const float* actee = (m & 1) ? obj1 : obj0;

    // Transposed, padded weights: Wt[n][k] = W[k][n]; row 50 of W carries bias.
    __shared__ half Wt1hi[64 * WST], Wt1lo[64 * WST];
    __shared__ half Wt2hi[64 * WST], Wt2lo[64 * WST];
    __shared__ float alph[128];

    for (int x = t; x < 64 * WST; x += TPB) {
        Wt1hi[x] = __float2half(0.f);  Wt1lo[x] = __float2half(0.f);
        Wt2hi[x] = __float2half(0.f);  Wt2lo[x] = __float2half(0.f);
    }
    __syncthreads();
    for (int x = t; x < 51 * 50; x += TPB) {
        int k = x / 50, n = x % 50;
        float w1 = (k < 50) ? gW1[m * 2500 + k * 50 + n] : gb1[m * 50 + n];
        float w2 = (k < 50) ? gW2[m * 2500 + k * 50 + n] : gb2[m * 50 + n];
        half hi, lo;
        split_w(w1, hi, lo);  Wt1hi[n * WST + k] = hi;  Wt1lo[n * WST + k] = lo;
        split_w(w2, hi, lo);  Wt2hi[n * WST + k] = hi;  Wt2lo[n * WST + k] = lo;
    }
    if (t < 128) alph[t] = actor[jc * 128 + t];

    // per-thread layer-1 constants at this thread's 16 fragment columns
    float pc[16], qc[16], rc[16];
#pragma unroll
    for (int kt = 0; kt < 4; kt++)
#pragma unroll
        for (int s = 0; s < 4; s++) {
            int col = kt * 16 + 2 * t4 + ((s >> 1) << 3) + (s & 1);
            int idx = kt * 4 + s;
            pc[idx] = (col < 50) ? gW0[m * 100 + col] : 0.f;        // W0[m][0][col]
            qc[idx] = (col < 50) ? gW0[m * 100 + 50 + col] : 0.f;   // W0[m][1][col]
            rc[idx] = (col < 50) ? gb0[m * 50 + col]
                                 : (col == 50 ? 1.f : 0.f);          // bias-feed col
        }
    const float betaA = actee[ib * 128 + w * 16 + g];
    const float betaB = actee[ib * 128 + w * 16 + g + 8];

    float Fr[28];
#pragma unroll
    for (int x = 0; x < 28; x++) Fr[x] = 0.f;

    // A3 kt=3 upper slots (k=56..63) always zero: nt=7 trimmed away
    uint32_t A3h[4][4];
    A3h[3][2] = A3h[3][3] = 0u;

    __syncthreads();    // the ONLY barrier before the writeback

    for (int jj = 0; jj < 128; ++jj) {
        const float al = alph[jj];

        // ---- layer 1 (rank-1 collapse) -> hi A fragments in registers ----
        // act residual (lo) dropped: averages out over the 1024-way j-sum.
        uint32_t A2h[4][4];
#pragma unroll
        for (int kt = 0; kt < 4; kt++) {
            const int b = kt * 4;
            float u0 = fmaf(al, pc[b + 0], rc[b + 0]);
            float u1 = fmaf(al, pc[b + 1], rc[b + 1]);
            float u2 = fmaf(al, pc[b + 2], rc[b + 2]);
            float u3 = fmaf(al, pc[b + 3], rc[b + 3]);
            float vA0 = fmaxf(fmaf(betaA, qc[b + 0], u0), 0.f);
            float vA1 = fmaxf(fmaf(betaA, qc[b + 1], u1), 0.f);
            float vA2 = fmaxf(fmaf(betaA, qc[b + 2], u2), 0.f);
            float vA3 = fmaxf(fmaf(betaA, qc[b + 3], u3), 0.f);
            float vB0 = fmaxf(fmaf(betaB, qc[b + 0], u0), 0.f);
            float vB1 = fmaxf(fmaf(betaB, qc[b + 1], u1), 0.f);
            float vB2 = fmaxf(fmaf(betaB, qc[b + 2], u2), 0.f);
            float vB3 = fmaxf(fmaf(betaB, qc[b + 3], u3), 0.f);
            A2h[kt][0] = pack2(vA0, vA1);
            A2h[kt][1] = pack2(vB0, vB1);
            A2h[kt][2] = pack2(vA2, vA3);
            A2h[kt][3] = pack2(vB2, vB3);
        }

        // ---- layer 2: z2 = H1 @ (W1hi + W1lo) + b1(col-50 feed) -> A3 ----
        // nt = 0..6 (cols 56..63 all-zero). Two n-tiles in flight.
#pragma unroll
        for (int np = 0; np < 4; np++) {
            const int ntA = 2 * np, ntB = 2 * np + 1;   // ntB==7 disabled at np=3
            float cA0[4] = {0.f,0.f,0.f,0.f}, cA1[4] = {0.f,0.f,0.f,0.f};
            float cB0[4] = {0.f,0.f,0.f,0.f}, cB1[4] = {0.f,0.f,0.f,0.f};
            const int roA = (ntA * 8 + g) * WST + 2 * t4;
            const int roB = (ntB * 8 + g) * WST + 2 * t4;
#pragma unroll
            for (int kt = 0; kt < 4; kt++) {
                const half* phA = Wt1hi + roA + kt * 16;
                const half* plA = Wt1lo + roA + kt * 16;
                uint32_t bhA0 = *(const uint32_t*)phA;
                uint32_t bhA1 = *(const uint32_t*)(phA + 8);
                uint32_t blA0 = *(const uint32_t*)plA;
                uint32_t blA1 = *(const uint32_t*)(plA + 8);
                float* ccA = (kt < 2) ? cA0 : cA1;
                mma16816(ccA, A2h[kt], bhA0, bhA1);
                mma16816(ccA, A2h[kt], blA0, blA1);
                if (np < 3) {
                    const half* phB = Wt1hi + roB + kt * 16;
                    const half* plB = Wt1lo + roB + kt * 16;
                    uint32_t bhB0 = *(const uint32_t*)phB;
                    uint32_t bhB1 = *(const uint32_t*)(phB + 8);
                    uint32_t blB0 = *(const uint32_t*)plB;
                    uint32_t blB1 = *(const uint32_t*)(plB + 8);
                    float* ccB = (kt < 2) ? cB0 : cB1;
                    mma16816(ccB, A2h[kt], bhB0, bhB1);
                    mma16816(ccB, A2h[kt], blB0, blB1);
                }
            }
            {
                const int col0 = ntA * 8 + 2 * t4;
                float v0 = (col0 == 50) ? 1.f : fmaxf(cA0[0] + cA1[0], 0.f);
                float v1 = fmaxf(cA0[1] + cA1[1], 0.f);       // odd col, never 50
                float v2 = (col0 == 50) ? 1.f : fmaxf(cA0[2] + cA1[2], 0.f);
                float v3 = fmaxf(cA0[3] + cA1[3], 0.f);
                const int kt2 = ntA >> 1, s0 = (ntA & 1) ? 2 : 0;
                A3h[kt2][s0]     = pack2(v0, v1);
                A3h[kt2][s0 + 1] = pack2(v2, v3);
            }
            if (np < 3) {
                const int col0 = ntB * 8 + 2 * t4;
                float v0 = (col0 == 50) ? 1.f : fmaxf(cB0[0] + cB1[0], 0.f);
                float v1 = fmaxf(cB0[1] + cB1[1], 0.f);
                float v2 = (col0 == 50) ? 1.f : fmaxf(cB0[2] + cB1[2], 0.f);
                float v3 = fmaxf(cB0[3] + cB1[3], 0.f);
                const int kt2 = ntB >> 1, s0 = (ntB & 1) ? 2 : 0;
                A3h[kt2][s0]     = pack2(v0, v1);
                A3h[kt2][s0 + 1] = pack2(v2, v3);
            }
        }

        // ---- layer 3: z3 = H2 @ (W2hi + W2lo) + b2, relu, accumulate ----
#pragma unroll
        for (int np = 0; np < 4; np++) {
            const int ntA = 2 * np, ntB = 2 * np + 1;
            float cA0[4] = {0.f,0.f,0.f,0.f}, cA1[4] = {0.f,0.f,0.f,0.f};
            float cB0[4] = {0.f,0.f,0.f,0.f}, cB1[4] = {0.f,0.f,0.f,0.f};
            const int roA = (ntA * 8 + g) * WST + 2 * t4;
            const int roB = (ntB * 8 + g) * WST + 2 * t4;
#pragma unroll
            for (int kt = 0; kt < 4; kt++) {
                const half* phA = Wt2hi + roA + kt * 16;
                const half* plA = Wt2lo + roA + kt * 16;
                uint32_t bhA0 = *(const uint32_t*)phA;
                uint32_t bhA1 = *(const uint32_t*)(phA + 8);
                uint32_t blA0 = *(const uint32_t*)plA;
                uint32_t blA1 = *(const uint32_t*)(plA + 8);
                float* ccA = (kt < 2) ? cA0 : cA1;
                mma16816(ccA, A3h[kt], bhA0, bhA1);
                mma16816(ccA, A3h[kt], blA0, blA1);
                if (np < 3) {
                    const half* phB = Wt2hi + roB + kt * 16;
                    const half* plB = Wt2lo + roB + kt * 16;
                    uint32_t bhB0 = *(const uint32_t*)phB;
                    uint32_t bhB1 = *(const uint32_t*)(phB + 8);
                    uint32_t blB0 = *(const uint32_t*)plB;
                    uint32_t blB1 = *(const uint32_t*)(plB + 8);
                    float* ccB = (kt < 2) ? cB0 : cB1;
                    mma16816(ccB, A3h[kt], bhB0, bhB1);
                    mma16816(ccB, A3h[kt], blB0, blB1);
                }
            }
            Fr[ntA * 4 + 0] += fmaxf(cA0[0] + cA1[0], 0.f);
            Fr[ntA * 4 + 1] += fmaxf(cA0[1] + cA1[1], 0.f);
            Fr[ntA * 4 + 2] += fmaxf(cA0[2] + cA1[2], 0.f);
            Fr[ntA * 4 + 3] += fmaxf(cA0[3] + cA1[3], 0.f);
            if (np < 3) {
                Fr[ntB * 4 + 0] += fmaxf(cB0[0] + cB1[0], 0.f);
                Fr[ntB * 4 + 1] += fmaxf(cB0[1] + cB1[1], 0.f);
                Fr[ntB * 4 + 2] += fmaxf(cB0[2] + cB1[2], 0.f);
                Fr[ntB * 4 + 3] += fmaxf(cB0[3] + cB1[3], 0.f);
            }
        }
    }

    // ---- deterministic partial writeback (W3 folded post-sum in finalize) ----
    const int i0 = ib * 128 + w * 16 + g;
    const long base = (long)(m * 8 + jc) * NOBJ;
#pragma unroll
    for (int nt = 0; nt < 7; nt++) {
        const int col0 = nt * 8 + 2 * t4;
        if (col0 < 50) {
            g_partial[(base + i0) * 50 + col0]     = Fr[nt * 4 + 0];
            g_partial[(base + i0 + 8) * 50 + col0] = Fr[nt * 4 + 2];
        }
        if (col0 + 1 < 50) {
            g_partial[(base + i0) * 50 + col0 + 1]     = Fr[nt * 4 + 1];
            g_partial[(base + i0 + 8) * 50 + col0 + 1] = Fr[nt * 4 + 3];
        }
    }
}

// warp-per-(c,i) finalize: jc-reduce, fold W3, apply head MLP
__global__ void __launch_bounds__(256)
finalize_kernel(const float* __restrict__ gW3, const float* __restrict__ gb3,
                const float* __restrict__ aW0, const float* __restrict__ ab0,
                const float* __restrict__ aW1, const float* __restrict__ ab1,
                float* __restrict__ out)
{
    const int warp = blockIdx.x * (blockDim.x >> 5) + (threadIdx.x >> 5);
    const int lane = threadIdx.x & 31;

    if (warp >= 2048) return;
    const int c = warp >> 10;
    const int i = warp & 1023;

    float F[20];
#pragma unroll
    for (int o = 0; o < 20; o++) F[o] = 0.f;

    for (int idx = lane; idx < 200; idx += 32) {
        const int a = idx / 50, k = idx % 50;
        const int mm = a * 2 + c;
        const float* gp = g_partial + ((long)(mm * 8) * NOBJ + i) * 50 + k;
        float s = 0.f;
#pragma unroll
        for (int jcc = 0; jcc < 8; jcc++) s += gp[(long)jcc * NOBJ * 50];
        const float* w3 = gW3 + mm * 1000 + k * 20;
#pragma unroll
        for (int o = 0; o < 20; o++) F[o] = fmaf(s, w3[o], F[o]);
    }
#pragma unroll
    for (int off = 16; off; off >>= 1)
#pragma unroll
        for (int o = 0; o < 20; o++)
            F[o] += __shfl_xor_sync(0xffffffffu, F[o], off);
#pragma unroll
    for (int o = 0; o < 20; o++) {
        float b = gb3[(0 + c) * 20 + o] + gb3[(2 + c) * 20 + o]
                + gb3[(4 + c) * 20 + o] + gb3[(6 + c) * 20 + o];
        F[o] += 1024.f * b;
    }

    float p = 0.f;
    for (int l = lane; l < 50; l += 32) {
        float h = ab0[c * 50 + l];
#pragma unroll
        for (int o = 0; o < 20; o++)
            h = fmaf(F[o], aW0[c * 1000 + o * 50 + l], h);
        p = fmaf(fmaxf(h, 0.f), aW1[c * 50 + l], p);
    }
#pragma unroll
    for (int off = 16; off; off >>= 1)
        p += __shfl_xor_sync(0xffffffffu, p, off);
    if (lane == 0) out[c * 1024 + i] = p + ab1[c];
}

extern "C" void kernel_launch(void* const* d_in, const int* in_sizes, int n_in,
                              void* d_out, int out_size)
{
    const float* obj0  = (const float*)d_in[0];
    const float* obj1  = (const float*)d_in[1];
    const float* prev0 = (const float*)d_in[2];
    const float* prev1 = (const float*)d_in[3];
    const float* gW0   = (const float*)d_in[4];
    const float* gb0   = (const float*)d_in[5];
    const float* gW1   = (const float*)d_in[6];
    const float* gb1   = (const float*)d_in[7];
    const float* gW2   = (const float*)d_in[8];
    const float* gb2   = (const float*)d_in[9];
    const float* gW3   = (const float*)d_in[10];
    const float* gb3   = (const float*)d_in[11];
    const float* aW0   = (const float*)d_in[12];
    const float* ab0   = (const float*)d_in[13];
    const float* aW1   = (const float*)d_in[14];
    const float* ab1   = (const float*)d_in[15];

    dim3 grid(8, 8, 8);   // (module, i-block, j-chunk)
    pair_kernel<<<grid, TPB>>>(obj0, obj1, prev0, prev1,
                               gW0, gb0, gW1, gb1, gW2, gb2);
    finalize_kernel<<<256, 256>>>(gW3, gb3, aW0, ab0, aW1, ab1, (float*)d_out);
}

// round 8
// speedup vs baseline: 2.1593x; 1.1606x over previous
#include <cuda_runtime.h>
#include <cuda_fp16.h>
#include <cstdint>

#define NOBJ 1024
#define TPB  256
#define WST  72        // SMEM weight row stride (halfs): 144B -> conflict-free

// partial[m][jc][i][50]  (fully overwritten every launch by the 512 CTAs)
__device__ float g_partial[8 * 8 * NOBJ * 50];

// ---------------------------------------------------------------------------
// mma.m16n8k16 row.col f32.f16.f16.f32
// A frag (4 b32): a0=(row g, k=2t4,2t4+1) a1=(g+8, same) a2=(g, +8) a3=(g+8, +8)
// B frag (2 b32): b0=(k=2t4,2t4+1, n=g)   b1=(k=+8, n=g)
// C frag (4 f32): c0=(g, n=2t4) c1=(g, 2t4+1) c2=(g+8, 2t4) c3=(g+8, 2t4+1)
// ---------------------------------------------------------------------------
__device__ __forceinline__ void mma16816(float c[4], const uint32_t a[4],
                                         uint32_t b0, uint32_t b1)
{
    asm("mma.sync.aligned.m16n8k16.row.col.f32.f16.f16.f32 "
        "{%0,%1,%2,%3}, {%4,%5,%6,%7}, {%8,%9}, {%0,%1,%2,%3};\n"
        : "+f"(c[0]), "+f"(c[1]), "+f"(c[2]), "+f"(c[3])
        : "r"(a[0]), "r"(a[1]), "r"(a[2]), "r"(a[3]), "r"(b0), "r"(b1));
}

__device__ __forceinline__ uint32_t pack2(float x, float y)
{
    half2 h = __floats2half2_rn(x, y);
    return *reinterpret_cast<uint32_t*>(&h);
}

__device__ __forceinline__ void split_w(float v, half& hi, half& lo)
{
    hi = __float2half_rn(v);
    lo = __float2half_rn(v - __half2float(hi));
}

__global__ void __launch_bounds__(TPB, 1)
pair_kernel(const float* __restrict__ obj0, const float* __restrict__ obj1,
            const float* __restrict__ prev0, const float* __restrict__ prev1,
            const float* __restrict__ gW0, const float* __restrict__ gb0,
            const float* __restrict__ gW1, const float* __restrict__ gb1,
            const float* __restrict__ gW2, const float* __restrict__ gb2)
{
    const int m  = blockIdx.x;   // module (actor class = m>>1, actee class = m&1)
    const int ib = blockIdx.y;   // i-block (128 actees)
    const int jc = blockIdx.z;   // j-chunk (128 actors)
    const int t  = threadIdx.x;
    const int w  = t >> 5;
    const int lane = t & 31;
    const int t4 = lane & 3;
    const int g  = lane >> 2;

    const int ac = m >> 1;
    const float* actor = (ac == 0) ? obj0 : (ac == 1) ? obj1 : (ac == 2) ? prev0 : prev1;
    const float* actee = (m & 1) ? obj1 : obj0;

    // Transposed, padded weights: Wt[n][k] = W[k][n], k = 0..47 only (MMA part).
    // k = 48, 49 and the bias enter via fp32 tail FMAs (W1tail/W2tail).
    __shared__ half Wt1hi[64 * WST], Wt1lo[64 * WST];
    __shared__ half Wt2hi[64 * WST], Wt2lo[64 * WST];
    __shared__ float4 W1tail[56], W2tail[56];   // [col] = {w[48][col], w[49][col], bias[col], 0}
    __shared__ float alph[128];

    for (int x = t; x < 64 * WST; x += TPB) {
        Wt1hi[x] = __float2half(0.f);  Wt1lo[x] = __float2half(0.f);
        Wt2hi[x] = __float2half(0.f);  Wt2lo[x] = __float2half(0.f);
    }
    __syncthreads();
    for (int x = t; x < 48 * 50; x += TPB) {
        int k = x / 50, n = x % 50;
        half hi, lo;
        split_w(gW1[m * 2500 + k * 50 + n], hi, lo);
        Wt1hi[n * WST + k] = hi;  Wt1lo[n * WST + k] = lo;
        split_w(gW2[m * 2500 + k * 50 + n], hi, lo);
        Wt2hi[n * WST + k] = hi;  Wt2lo[n * WST + k] = lo;
    }
    if (t < 56) {
        bool real = t < 50;
        W1tail[t] = make_float4(real ? gW1[m * 2500 + 48 * 50 + t] : 0.f,
                                real ? gW1[m * 2500 + 49 * 50 + t] : 0.f,
                                real ? gb1[m * 50 + t] : 0.f, 0.f);
        W2tail[t] = make_float4(real ? gW2[m * 2500 + 48 * 50 + t] : 0.f,
                                real ? gW2[m * 2500 + 49 * 50 + t] : 0.f,
                                real ? gb2[m * 50 + t] : 0.f, 0.f);
    }
    if (t < 128) alph[t] = actor[jc * 128 + t];

    // per-thread layer-1 constants at this thread's 12 fragment columns (k 0..47)
    float pc[12], qc[12], rc[12];
#pragma unroll
    for (int kt = 0; kt < 3; kt++)
#pragma unroll
        for (int s = 0; s < 4; s++) {
            int col = kt * 16 + 2 * t4 + ((s >> 1) << 3) + (s & 1);   // < 48
            int idx = kt * 4 + s;
            pc[idx] = gW0[m * 100 + col];        // W0[m][0][col]
            qc[idx] = gW0[m * 100 + 50 + col];   // W0[m][1][col]
            rc[idx] = gb0[m * 50 + col];
        }
    // tail columns 48, 49 (fp32, shared by all threads)
    const float p48 = gW0[m * 100 + 48], p49 = gW0[m * 100 + 49];
    const float q48 = gW0[m * 100 + 50 + 48], q49 = gW0[m * 100 + 50 + 49];
    const float r48 = gb0[m * 50 + 48], r49 = gb0[m * 50 + 49];

    const float betaA = actee[ib * 128 + w * 16 + g];
    const float betaB = actee[ib * 128 + w * 16 + g + 8];

    float Fr[28];
#pragma unroll
    for (int x = 0; x < 28; x++) Fr[x] = 0.f;

    __syncthreads();    // the ONLY barrier before the writeback

    for (int jj = 0; jj < 128; ++jj) {
        const float al = alph[jj];

        // ---- layer 1 (rank-1 collapse) -> hi A fragments (k 0..47) ----
        uint32_t A2h[3][4];
#pragma unroll
        for (int kt = 0; kt < 3; kt++) {
            const int b = kt * 4;
            float u0 = fmaf(al, pc[b + 0], rc[b + 0]);
            float u1 = fmaf(al, pc[b + 1], rc[b + 1]);
            float u2 = fmaf(al, pc[b + 2], rc[b + 2]);
            float u3 = fmaf(al, pc[b + 3], rc[b + 3]);
            float vA0 = fmaxf(fmaf(betaA, qc[b + 0], u0), 0.f);
            float vA1 = fmaxf(fmaf(betaA, qc[b + 1], u1), 0.f);
            float vA2 = fmaxf(fmaf(betaA, qc[b + 2], u2), 0.f);
            float vA3 = fmaxf(fmaf(betaA, qc[b + 3], u3), 0.f);
            float vB0 = fmaxf(fmaf(betaB, qc[b + 0], u0), 0.f);
            float vB1 = fmaxf(fmaf(betaB, qc[b + 1], u1), 0.f);
            float vB2 = fmaxf(fmaf(betaB, qc[b + 2], u2), 0.f);
            float vB3 = fmaxf(fmaf(betaB, qc[b + 3], u3), 0.f);
            A2h[kt][0] = pack2(vA0, vA1);
            A2h[kt][1] = pack2(vB0, vB1);
            A2h[kt][2] = pack2(vA2, vA3);
            A2h[kt][3] = pack2(vB2, vB3);
        }
        // layer-1 tail columns 48, 49 in fp32 (feed the rank-3 correction)
        const float u48 = fmaf(al, p48, r48), u49 = fmaf(al, p49, r49);
        const float h1A48 = fmaxf(fmaf(betaA, q48, u48), 0.f);
        const float h1A49 = fmaxf(fmaf(betaA, q49, u49), 0.f);
        const float h1B48 = fmaxf(fmaf(betaB, q48, u48), 0.f);
        const float h1B49 = fmaxf(fmaf(betaB, q49, u49), 0.f);

        // ---- layer 2: z2 = H1[:,0:48] @ W1 (MMA) + rank-3 fp32 tail ----
        uint32_t A3h[3][4];
        uint32_t hgA = 0, hgB = 0;      // packed h2 cols (48,49), rows g / g+8
#pragma unroll
        for (int np = 0; np < 4; np++) {
            const int ntA = 2 * np, ntB = 2 * np + 1;   // ntB==7 disabled at np=3
            float cA0[4] = {0.f,0.f,0.f,0.f}, cA1[4] = {0.f,0.f,0.f,0.f};
            float cB0[4] = {0.f,0.f,0.f,0.f}, cB1[4] = {0.f,0.f,0.f,0.f};
            const int roA = (ntA * 8 + g) * WST + 2 * t4;
            const int roB = (ntB * 8 + g) * WST + 2 * t4;
#pragma unroll
            for (int kt = 0; kt < 3; kt++) {
                const half* phA = Wt1hi + roA + kt * 16;
                const half* plA = Wt1lo + roA + kt * 16;
                uint32_t bhA0 = *(const uint32_t*)phA;
                uint32_t bhA1 = *(const uint32_t*)(phA + 8);
                uint32_t blA0 = *(const uint32_t*)plA;
                uint32_t blA1 = *(const uint32_t*)(plA + 8);
                float* ccA = (kt < 2) ? cA0 : cA1;
                mma16816(ccA, A2h[kt], bhA0, bhA1);
                mma16816(ccA, A2h[kt], blA0, blA1);
                if (np < 3) {
                    const half* phB = Wt1hi + roB + kt * 16;
                    const half* plB = Wt1lo + roB + kt * 16;
                    uint32_t bhB0 = *(const uint32_t*)phB;
                    uint32_t bhB1 = *(const uint32_t*)(phB + 8);
                    uint32_t blB0 = *(const uint32_t*)plB;
                    uint32_t blB1 = *(const uint32_t*)(plB + 8);
                    float* ccB = (kt < 2) ? cB0 : cB1;
                    mma16816(ccB, A2h[kt], bhB0, bhB1);
                    mma16816(ccB, A2h[kt], blB0, blB1);
                }
            }
            {   // tile ntA epilogue: rank-3 tail + bias + relu
                const int col0 = ntA * 8 + 2 * t4;
                float4 Ta = W1tail[col0], Tb = W1tail[col0 + 1];
                float z0 = cA0[0] + cA1[0] + h1A48 * Ta.x + h1A49 * Ta.y + Ta.z;
                float z1 = cA0[1] + cA1[1] + h1A48 * Tb.x + h1A49 * Tb.y + Tb.z;
                float z2 = cA0[2] + cA1[2] + h1B48 * Ta.x + h1B49 * Ta.y + Ta.z;
                float z3 = cA0[3] + cA1[3] + h1B48 * Tb.x + h1B49 * Tb.y + Tb.z;
                float v0 = fmaxf(z0, 0.f), v1 = fmaxf(z1, 0.f);
                float v2 = fmaxf(z2, 0.f), v3 = fmaxf(z3, 0.f);
                if (np < 3) {
                    const int kt2 = ntA >> 1;
                    A3h[kt2][0] = pack2(v0, v1);
                    A3h[kt2][1] = pack2(v2, v3);
                } else {     // ntA = 6: cols 48,49 live at t4==0 -> keep packed
                    hgA = pack2(v0, v1);
                    hgB = pack2(v2, v3);
                }
            }
            if (np < 3) {    // tile ntB epilogue
                const int col0 = ntB * 8 + 2 * t4;
                float4 Ta = W1tail[col0], Tb = W1tail[col0 + 1];
                float z0 = cB0[0] + cB1[0] + h1A48 * Ta.x + h1A49 * Ta.y + Ta.z;
                float z1 = cB0[1] + cB1[1] + h1A48 * Tb.x + h1A49 * Tb.y + Tb.z;
                float z2 = cB0[2] + cB1[2] + h1B48 * Ta.x + h1B49 * Ta.y + Ta.z;
                float z3 = cB0[3] + cB1[3] + h1B48 * Tb.x + h1B49 * Tb.y + Tb.z;
                const int kt2 = ntB >> 1;
                A3h[kt2][2] = pack2(fmaxf(z0, 0.f), fmaxf(z1, 0.f));
                A3h[kt2][3] = pack2(fmaxf(z2, 0.f), fmaxf(z3, 0.f));
            }
        }

        // broadcast h2 cols 48,49 (held by t4==0) to the whole quad
        {
            const int src = lane & ~3;
            uint32_t sA = __shfl_sync(0xffffffffu, hgA, src);
            uint32_t sB = __shfl_sync(0xffffffffu, hgB, src);
            half2 hA = *reinterpret_cast<half2*>(&sA);
            half2 hB = *reinterpret_cast<half2*>(&sB);
            float2 fA = __half22float2(hA);
            float2 fB = __half22float2(hB);
            const float h2A48 = fA.x, h2A49 = fA.y;   // rows g
            const float h2B48 = fB.x, h2B49 = fB.y;   // rows g+8

            // ---- layer 3: z3 = H2[:,0:48] @ W2 (MMA) + rank-3 tail ----
#pragma unroll
            for (int np = 0; np < 4; np++) {
                const int ntA = 2 * np, ntB = 2 * np + 1;
                float cA0[4] = {0.f,0.f,0.f,0.f}, cA1[4] = {0.f,0.f,0.f,0.f};
                float cB0[4] = {0.f,0.f,0.f,0.f}, cB1[4] = {0.f,0.f,0.f,0.f};
                const int roA = (ntA * 8 + g) * WST + 2 * t4;
                const int roB = (ntB * 8 + g) * WST + 2 * t4;
#pragma unroll
                for (int kt = 0; kt < 3; kt++) {
                    const half* phA = Wt2hi + roA + kt * 16;
                    const half* plA = Wt2lo + roA + kt * 16;
                    uint32_t bhA0 = *(const uint32_t*)phA;
                    uint32_t bhA1 = *(const uint32_t*)(phA + 8);
                    uint32_t blA0 = *(const uint32_t*)plA;
                    uint32_t blA1 = *(const uint32_t*)(plA + 8);
                    float* ccA = (kt < 2) ? cA0 : cA1;
                    mma16816(ccA, A3h[kt], bhA0, bhA1);
                    mma16816(ccA, A3h[kt], blA0, blA1);
                    if (np < 3) {
                        const half* phB = Wt2hi + roB + kt * 16;
                        const half* plB = Wt2lo + roB + kt * 16;
                        uint32_t bhB0 = *(const uint32_t*)phB;
                        uint32_t bhB1 = *(const uint32_t*)(phB + 8);
                        uint32_t blB0 = *(const uint32_t*)plB;
                        uint32_t blB1 = *(const uint32_t*)(plB + 8);
                        float* ccB = (kt < 2) ? cB0 : cB1;
                        mma16816(ccB, A3h[kt], bhB0, bhB1);
                        mma16816(ccB, A3h[kt], blB0, blB1);
                    }
                }
                {
                    const int col0 = ntA * 8 + 2 * t4;
                    float4 Ta = W2tail[col0], Tb = W2tail[col0 + 1];
                    float z0 = cA0[0] + cA1[0] + h2A48 * Ta.x + h2A49 * Ta.y + Ta.z;
                    float z1 = cA0[1] + cA1[1] + h2A48 * Tb.x + h2A49 * Tb.y + Tb.z;
                    float z2 = cA0[2] + cA1[2] + h2B48 * Ta.x + h2B49 * Ta.y + Ta.z;
                    float z3 = cA0[3] + cA1[3] + h2B48 * Tb.x + h2B49 * Tb.y + Tb.z;
                    Fr[ntA * 4 + 0] += fmaxf(z0, 0.f);
                    Fr[ntA * 4 + 1] += fmaxf(z1, 0.f);
                    Fr[ntA * 4 + 2] += fmaxf(z2, 0.f);
                    Fr[ntA * 4 + 3] += fmaxf(z3, 0.f);
                }
                if (np < 3) {
                    const int col0 = ntB * 8 + 2 * t4;
                    float4 Ta = W2tail[col0], Tb = W2tail[col0 + 1];
                    float z0 = cB0[0] + cB1[0] + h2A48 * Ta.x + h2A49 * Ta.y + Ta.z;
                    float z1 = cB0[1] + cB1[1] + h2A48 * Tb.x + h2A49 * Tb.y + Tb.z;
                    float z2 = cB0[2] + cB1[2] + h2B48 * Ta.x + h2B49 * Ta.y + Ta.z;
                    float z3 = cB0[3] + cB1[3] + h2B48 * Tb.x + h2B49 * Tb.y + Tb.z;
                    Fr[ntB * 4 + 0] += fmaxf(z0, 0.f);
                    Fr[ntB * 4 + 1] += fmaxf(z1, 0.f);
                    Fr[ntB * 4 + 2] += fmaxf(z2, 0.f);
                    Fr[ntB * 4 + 3] += fmaxf(z3, 0.f);
                }
            }
        }
    }

    // ---- deterministic partial writeback (W3 folded post-sum in finalize) ----
    const int i0 = ib * 128 + w * 16 + g;
    const long base = (long)(m * 8 + jc) * NOBJ;
#pragma unroll
    for (int nt = 0; nt < 7; nt++) {
        const int col0 = nt * 8 + 2 * t4;
        if (col0 < 50) {
            g_partial[(base + i0) * 50 + col0]     = Fr[nt * 4 + 0];
            g_partial[(base + i0 + 8) * 50 + col0] = Fr[nt * 4 + 2];
        }
        if (col0 + 1 < 50) {
            g_partial[(base + i0) * 50 + col0 + 1]     = Fr[nt * 4 + 1];
            g_partial[(base + i0 + 8) * 50 + col0 + 1] = Fr[nt * 4 + 3];
        }
    }
}

// warp-per-(c,i) finalize: jc-reduce, fold W3, apply head MLP
__global__ void __launch_bounds__(256)
finalize_kernel(const float* __restrict__ gW3, const float* __restrict__ gb3,
                const float* __restrict__ aW0, const float* __restrict__ ab0,
                const float* __restrict__ aW1, const float* __restrict__ ab1,
                float* __restrict__ out)
{
    const int warp = blockIdx.x * (blockDim.x >> 5) + (threadIdx.x >> 5);
    const int lane = threadIdx.x & 31;

    if (warp >= 2048) return;
    const int c = warp >> 10;
    const int i = warp & 1023;

    float F[20];
#pragma unroll
    for (int o = 0; o < 20; o++) F[o] = 0.f;

    for (int idx = lane; idx < 200; idx += 32) {
        const int a = idx / 50, k = idx % 50;
        const int mm = a * 2 + c;
        const float* gp = g_partial + ((long)(mm * 8) * NOBJ + i) * 50 + k;
        float s = 0.f;
#pragma unroll
        for (int jcc = 0; jcc < 8; jcc++) s += gp[(long)jcc * NOBJ * 50];
        const float* w3 = gW3 + mm * 1000 + k * 20;
#pragma unroll
        for (int o = 0; o < 20; o++) F[o] = fmaf(s, w3[o], F[o]);
    }
#pragma unroll
    for (int off = 16; off; off >>= 1)
#pragma unroll
        for (int o = 0; o < 20; o++)
            F[o] += __shfl_xor_sync(0xffffffffu, F[o], off);
#pragma unroll
    for (int o = 0; o < 20; o++) {
        float b = gb3[(0 + c) * 20 + o] + gb3[(2 + c) * 20 + o]
                + gb3[(4 + c) * 20 + o] + gb3[(6 + c) * 20 + o];
        F[o] += 1024.f * b;
    }

    float p = 0.f;
    for (int l = lane; l < 50; l += 32) {
        float h = ab0[c * 50 + l];
#pragma unroll
        for (int o = 0; o < 20; o++)
            h = fmaf(F[o], aW0[c * 1000 + o * 50 + l], h);
        p = fmaf(fmaxf(h, 0.f), aW1[c * 50 + l], p);
    }
#pragma unroll
    for (int off = 16; off; off >>= 1)
        p += __shfl_xor_sync(0xffffffffu, p, off);
    if (lane == 0) out[c * 1024 + i] = p + ab1[c];
}

extern "C" void kernel_launch(void* const* d_in, const int* in_sizes, int n_in,
                              void* d_out, int out_size)
{
    const float* obj0  = (const float*)d_in[0];
    const float* obj1  = (const float*)d_in[1];
    const float* prev0 = (const float*)d_in[2];
    const float* prev1 = (const float*)d_in[3];
    const float* gW0   = (const float*)d_in[4];
    const float* gb0   = (const float*)d_in[5];
    const float* gW1   = (const float*)d_in[6];
    const float* gb1   = (const float*)d_in[7];
    const float* gW2   = (const float*)d_in[8];
    const float* gb2   = (const float*)d_in[9];
    const float* gW3   = (const float*)d_in[10];
    const float* gb3   = (const float*)d_in[11];
    const float* aW0   = (const float*)d_in[12];
    const float* ab0   = (const float*)d_in[13];
    const float* aW1   = (const float*)d_in[14];
    const float* ab1   = (const float*)d_in[15];

    dim3 grid(8, 8, 8);   // (module, i-block, j-chunk)
    pair_kernel<<<grid, TPB>>>(obj0, obj1, prev0, prev1,
                               gW0, gb0, gW1, gb1, gW2, gb2);
    finalize_kernel<<<256, 256>>>(gW3, gb3, aW0, ab0, aW1, ab1, (float*)d_out);
}

// round 9
// speedup vs baseline: 3.9238x; 1.8171x over previous
#include <cuda_runtime.h>
#include <cuda_fp16.h>
#include <cstdint>

#define NOBJ 1024
#define TPB  256
#define JB   64        // actors per CTA chunk (16 chunks -> 1024 CTAs, 7 waves)
#define WST  72        // SMEM weight row stride (halfs): 144B -> conflict-free

// partial[m][jc][i][50]  (fully overwritten every launch by the 1024 CTAs)
__device__ float g_partial[8 * 16 * NOBJ * 50];

// ---------------------------------------------------------------------------
// mma.m16n8k16 row.col f32.f16.f16.f32
// A frag (4 b32): a0=(row g, k=2t4,2t4+1) a1=(g+8, same) a2=(g, +8) a3=(g+8, +8)
// B frag (2 b32): b0=(k=2t4,2t4+1, n=g)   b1=(k=+8, n=g)
// C frag (4 f32): c0=(g, n=2t4) c1=(g, 2t4+1) c2=(g+8, 2t4) c3=(g+8, 2t4+1)
// ---------------------------------------------------------------------------
__device__ __forceinline__ void mma16816(float c[4], const uint32_t a[4],
                                         uint32_t b0, uint32_t b1)
{
    asm("mma.sync.aligned.m16n8k16.row.col.f32.f16.f16.f32 "
        "{%0,%1,%2,%3}, {%4,%5,%6,%7}, {%8,%9}, {%0,%1,%2,%3};\n"
        : "+f"(c[0]), "+f"(c[1]), "+f"(c[2]), "+f"(c[3])
        : "r"(a[0]), "r"(a[1]), "r"(a[2]), "r"(a[3]), "r"(b0), "r"(b1));
}

__device__ __forceinline__ uint32_t pack2(float x, float y)
{
    half2 h = __floats2half2_rn(x, y);
    return *reinterpret_cast<uint32_t*>(&h);
}

// dithered pair: w_e = rn(w); w_o = rn(2w - w_e)  (error of w_o ~ -error(w_e))
__device__ __forceinline__ void dither_w(float v, half& we, half& wo)
{
    we = __float2half_rn(v);
    wo = __float2half_rn(2.f * v - __half2float(we));
}

__global__ void __launch_bounds__(TPB, 1)
pair_kernel(const float* __restrict__ obj0, const float* __restrict__ obj1,
            const float* __restrict__ prev0, const float* __restrict__ prev1,
            const float* __restrict__ gW0, const float* __restrict__ gb0,
            const float* __restrict__ gW1, const float* __restrict__ gb1,
            const float* __restrict__ gW2, const float* __restrict__ gb2)
{
    const int m  = blockIdx.x;   // module (actor class = m>>1, actee class = m&1)
    const int ib = blockIdx.y;   // i-block (128 actees)
    const int jc = blockIdx.z;   // j-chunk (64 actors, 16 chunks)
    const int t  = threadIdx.x;
    const int w  = t >> 5;
    const int lane = t & 31;
    const int t4 = lane & 3;
    const int g  = lane >> 2;

    const int ac = m >> 1;
    const float* actor = (ac == 0) ? obj0 : (ac == 1) ? obj1 : (ac == 2) ? prev0 : prev1;
    const float* actee = (m & 1) ? obj1 : obj0;

    // Transposed, padded weights: Wt[n][k] = W[k][n]; row k=50 carries the bias
    // (fed by the constant-1.0 col-50 of H). Even/odd dithered copies: the fp16
    // rounding error flips sign with j-parity and averages out of the j-sum.
    __shared__ half Wt1e[64 * WST], Wt1o[64 * WST];
    __shared__ half Wt2e[64 * WST], Wt2o[64 * WST];
    __shared__ float alph[JB];

    for (int x = t; x < 64 * WST; x += TPB) {
        Wt1e[x] = __float2half(0.f);  Wt1o[x] = __float2half(0.f);
        Wt2e[x] = __float2half(0.f);  Wt2o[x] = __float2half(0.f);
    }
    __syncthreads();
    for (int x = t; x < 51 * 50; x += TPB) {
        int k = x / 50, n = x % 50;
        float w1 = (k < 50) ? gW1[m * 2500 + k * 50 + n] : gb1[m * 50 + n];
        float w2 = (k < 50) ? gW2[m * 2500 + k * 50 + n] : gb2[m * 50 + n];
        half we, wo;
        dither_w(w1, we, wo);  Wt1e[n * WST + k] = we;  Wt1o[n * WST + k] = wo;
        dither_w(w2, we, wo);  Wt2e[n * WST + k] = we;  Wt2o[n * WST + k] = wo;
    }
    if (t < JB) alph[t] = actor[jc * JB + t];

    // per-thread layer-1 constants at this thread's 16 fragment columns
    float pc[16], qc[16], rc[16];
#pragma unroll
    for (int kt = 0; kt < 4; kt++)
#pragma unroll
        for (int s = 0; s < 4; s++) {
            int col = kt * 16 + 2 * t4 + ((s >> 1) << 3) + (s & 1);
            int idx = kt * 4 + s;
            pc[idx] = (col < 50) ? gW0[m * 100 + col] : 0.f;        // W0[m][0][col]
            qc[idx] = (col < 50) ? gW0[m * 100 + 50 + col] : 0.f;   // W0[m][1][col]
            rc[idx] = (col < 50) ? gb0[m * 50 + col]
                                 : (col == 50 ? 1.f : 0.f);          // bias-feed col
        }
    const float betaA = actee[ib * 128 + w * 16 + g];
    const float betaB = actee[ib * 128 + w * 16 + g + 8];

    float Fr[28];
#pragma unroll
    for (int x = 0; x < 28; x++) Fr[x] = 0.f;

    // A3 kt=3 upper slots (k=56..63) always zero: nt=7 trimmed away
    uint32_t A3h[4][4];
    A3h[3][2] = A3h[3][3] = 0u;

    __syncthreads();    // the ONLY barrier before the writeback

    for (int jj = 0; jj < JB; ++jj) {
        const float al = alph[jj];
        // parity-selected dithered weight set
        const half* __restrict__ W1 = (jj & 1) ? Wt1o : Wt1e;
        const half* __restrict__ W2 = (jj & 1) ? Wt2o : Wt2e;

        // ---- layer 1 (rank-1 collapse) -> hi A fragments in registers ----
        uint32_t A2h[4][4];
#pragma unroll
        for (int kt = 0; kt < 4; kt++) {
            const int b = kt * 4;
            float u0 = fmaf(al, pc[b + 0], rc[b + 0]);
            float u1 = fmaf(al, pc[b + 1], rc[b + 1]);
            float u2 = fmaf(al, pc[b + 2], rc[b + 2]);
            float u3 = fmaf(al, pc[b + 3], rc[b + 3]);
            float vA0 = fmaxf(fmaf(betaA, qc[b + 0], u0), 0.f);
            float vA1 = fmaxf(fmaf(betaA, qc[b + 1], u1), 0.f);
            float vA2 = fmaxf(fmaf(betaA, qc[b + 2], u2), 0.f);
            float vA3 = fmaxf(fmaf(betaA, qc[b + 3], u3), 0.f);
            float vB0 = fmaxf(fmaf(betaB, qc[b + 0], u0), 0.f);
            float vB1 = fmaxf(fmaf(betaB, qc[b + 1], u1), 0.f);
            float vB2 = fmaxf(fmaf(betaB, qc[b + 2], u2), 0.f);
            float vB3 = fmaxf(fmaf(betaB, qc[b + 3], u3), 0.f);
            A2h[kt][0] = pack2(vA0, vA1);
            A2h[kt][1] = pack2(vB0, vB1);
            A2h[kt][2] = pack2(vA2, vA3);
            A2h[kt][3] = pack2(vB2, vB3);
        }

        // ---- layer 2: z2 = H1 @ W1d (+b1 via col-50 feed), chain into A3 ----
        // nt = 0..6 (cols 56..63 all-zero). Two n-tiles in flight.
#pragma unroll
        for (int np = 0; np < 4; np++) {
            const int ntA = 2 * np, ntB = 2 * np + 1;   // ntB==7 disabled at np=3
            float cA0[4] = {0.f,0.f,0.f,0.f}, cA1[4] = {0.f,0.f,0.f,0.f};
            float cB0[4] = {0.f,0.f,0.f,0.f}, cB1[4] = {0.f,0.f,0.f,0.f};
            const int roA = (ntA * 8 + g) * WST + 2 * t4;
            const int roB = (ntB * 8 + g) * WST + 2 * t4;
#pragma unroll
            for (int kt = 0; kt < 4; kt++) {
                const half* phA = W1 + roA + kt * 16;
                uint32_t bA0 = *(const uint32_t*)phA;
                uint32_t bA1 = *(const uint32_t*)(phA + 8);
                mma16816((kt < 2) ? cA0 : cA1, A2h[kt], bA0, bA1);
                if (np < 3) {
                    const half* phB = W1 + roB + kt * 16;
                    uint32_t bB0 = *(const uint32_t*)phB;
                    uint32_t bB1 = *(const uint32_t*)(phB + 8);
                    mma16816((kt < 2) ? cB0 : cB1, A2h[kt], bB0, bB1);
                }
            }
            {
                const int col0 = ntA * 8 + 2 * t4;
                float v0 = (col0 == 50) ? 1.f : fmaxf(cA0[0] + cA1[0], 0.f);
                float v1 = fmaxf(cA0[1] + cA1[1], 0.f);       // odd col, never 50
                float v2 = (col0 == 50) ? 1.f : fmaxf(cA0[2] + cA1[2], 0.f);
                float v3 = fmaxf(cA0[3] + cA1[3], 0.f);
                const int kt2 = ntA >> 1, s0 = (ntA & 1) ? 2 : 0;
                A3h[kt2][s0]     = pack2(v0, v1);
                A3h[kt2][s0 + 1] = pack2(v2, v3);
            }
            if (np < 3) {
                const int col0 = ntB * 8 + 2 * t4;
                float v0 = (col0 == 50) ? 1.f : fmaxf(cB0[0] + cB1[0], 0.f);
                float v1 = fmaxf(cB0[1] + cB1[1], 0.f);
                float v2 = (col0 == 50) ? 1.f : fmaxf(cB0[2] + cB1[2], 0.f);
                float v3 = fmaxf(cB0[3] + cB1[3], 0.f);
                const int kt2 = ntB >> 1, s0 = (ntB & 1) ? 2 : 0;
                A3h[kt2][s0]     = pack2(v0, v1);
                A3h[kt2][s0 + 1] = pack2(v2, v3);
            }
        }

        // ---- layer 3: z3 = H2 @ W2d (+b2 via col-50 feed), relu, accum ----
#pragma unroll
        for (int np = 0; np < 4; np++) {
            const int ntA = 2 * np, ntB = 2 * np + 1;
            float cA0[4] = {0.f,0.f,0.f,0.f}, cA1[4] = {0.f,0.f,0.f,0.f};
            float cB0[4] = {0.f,0.f,0.f,0.f}, cB1[4] = {0.f,0.f,0.f,0.f};
            const int roA = (ntA * 8 + g) * WST + 2 * t4;
            const int roB = (ntB * 8 + g) * WST + 2 * t4;
#pragma unroll
            for (int kt = 0; kt < 4; kt++) {
                const half* phA = W2 + roA + kt * 16;
                uint32_t bA0 = *(const uint32_t*)phA;
                uint32_t bA1 = *(const uint32_t*)(phA + 8);
                mma16816((kt < 2) ? cA0 : cA1, A3h[kt], bA0, bA1);
                if (np < 3) {
                    const half* phB = W2 + roB + kt * 16;
                    uint32_t bB0 = *(const uint32_t*)phB;
                    uint32_t bB1 = *(const uint32_t*)(phB + 8);
                    mma16816((kt < 2) ? cB0 : cB1, A3h[kt], bB0, bB1);
                }
            }
            Fr[ntA * 4 + 0] += fmaxf(cA0[0] + cA1[0], 0.f);
            Fr[ntA * 4 + 1] += fmaxf(cA0[1] + cA1[1], 0.f);
            Fr[ntA * 4 + 2] += fmaxf(cA0[2] + cA1[2], 0.f);
            Fr[ntA * 4 + 3] += fmaxf(cA0[3] + cA1[3], 0.f);
            if (np < 3) {
                Fr[ntB * 4 + 0] += fmaxf(cB0[0] + cB1[0], 0.f);
                Fr[ntB * 4 + 1] += fmaxf(cB0[1] + cB1[1], 0.f);
                Fr[ntB * 4 + 2] += fmaxf(cB0[2] + cB1[2], 0.f);
                Fr[ntB * 4 + 3] += fmaxf(cB0[3] + cB1[3], 0.f);
            }
        }
    }

    // ---- deterministic partial writeback (W3 folded post-sum in finalize) ----
    const int i0 = ib * 128 + w * 16 + g;
    const long base = (long)(m * 16 + jc) * NOBJ;
#pragma unroll
    for (int nt = 0; nt < 7; nt++) {
        const int col0 = nt * 8 + 2 * t4;
        if (col0 < 50) {
            g_partial[(base + i0) * 50 + col0]     = Fr[nt * 4 + 0];
            g_partial[(base + i0 + 8) * 50 + col0] = Fr[nt * 4 + 2];
        }
        if (col0 + 1 < 50) {
            g_partial[(base + i0) * 50 + col0 + 1]     = Fr[nt * 4 + 1];
            g_partial[(base + i0 + 8) * 50 + col0 + 1] = Fr[nt * 4 + 3];
        }
    }
}

// warp-per-(c,i) finalize: jc-reduce, fold W3, apply head MLP
__global__ void __launch_bounds__(256)
finalize_kernel(const float* __restrict__ gW3, const float* __restrict__ gb3,
                const float* __restrict__ aW0, const float* __restrict__ ab0,
                const float* __restrict__ aW1, const float* __restrict__ ab1,
                float* __restrict__ out)
{
    const int warp = blockIdx.x * (blockDim.x >> 5) + (threadIdx.x >> 5);
    const int lane = threadIdx.x & 31;

    if (warp >= 2048) return;
    const int c = warp >> 10;
    const int i = warp & 1023;

    float F[20];
#pragma unroll
    for (int o = 0; o < 20; o++) F[o] = 0.f;

    for (int idx = lane; idx < 200; idx += 32) {
        const int a = idx / 50, k = idx % 50;
        const int mm = a * 2 + c;
        const float* gp = g_partial + ((long)(mm * 16) * NOBJ + i) * 50 + k;
        float s = 0.f;
#pragma unroll
        for (int jcc = 0; jcc < 16; jcc++) s += gp[(long)jcc * NOBJ * 50];
        const float* w3 = gW3 + mm * 1000 + k * 20;
#pragma unroll
        for (int o = 0; o < 20; o++) F[o] = fmaf(s, w3[o], F[o]);
    }
#pragma unroll
    for (int off = 16; off; off >>= 1)
#pragma unroll
        for (int o = 0; o < 20; o++)
            F[o] += __shfl_xor_sync(0xffffffffu, F[o], off);
#pragma unroll
    for (int o = 0; o < 20; o++) {
        float b = gb3[(0 + c) * 20 + o] + gb3[(2 + c) * 20 + o]
                + gb3[(4 + c) * 20 + o] + gb3[(6 + c) * 20 + o];
        F[o] += 1024.f * b;
    }

    float p = 0.f;
    for (int l = lane; l < 50; l += 32) {
        float h = ab0[c * 50 + l];
#pragma unroll
        for (int o = 0; o < 20; o++)
            h = fmaf(F[o], aW0[c * 1000 + o * 50 + l], h);
        p = fmaf(fmaxf(h, 0.f), aW1[c * 50 + l], p);
    }
#pragma unroll
    for (int off = 16; off; off >>= 1)
        p += __shfl_xor_sync(0xffffffffu, p, off);
    if (lane == 0) out[c * 1024 + i] = p + ab1[c];
}

extern "C" void kernel_launch(void* const* d_in, const int* in_sizes, int n_in,
                              void* d_out, int out_size)
{
    const float* obj0  = (const float*)d_in[0];
    const float* obj1  = (const float*)d_in[1];
    const float* prev0 = (const float*)d_in[2];
    const float* prev1 = (const float*)d_in[3];
    const float* gW0   = (const float*)d_in[4];
    const float* gb0   = (const float*)d_in[5];
    const float* gW1   = (const float*)d_in[6];
    const float* gb1   = (const float*)d_in[7];
    const float* gW2   = (const float*)d_in[8];
    const float* gb2   = (const float*)d_in[9];
    const float* gW3   = (const float*)d_in[10];
    const float* gb3   = (const float*)d_in[11];
    const float* aW0   = (const float*)d_in[12];
    const float* ab0   = (const float*)d_in[13];
    const float* aW1   = (const float*)d_in[14];
    const float* ab1   = (const float*)d_in[15];

    dim3 grid(8, 8, 16);   // (module, i-block, j-chunk of 64) -> 1024 CTAs
    pair_kernel<<<grid, TPB>>>(obj0, obj1, prev0, prev1,
                               gW0, gb0, gW1, gb1, gW2, gb2);
    finalize_kernel<<<256, 256>>>(gW3, gb3, aW0, ab0, aW1, ab1, (float*)d_out);
}